// round 1
// baseline (speedup 1.0000x reference)
#include <cuda_runtime.h>
#include <math.h>

#ifndef M_PI
#define M_PI 3.14159265358979323846
#endif

#define DEPTH 5
#define HID 128
#define CODE_D 400
#define NFREQ 9
#define NPTS 32768
#define NB 8
#define TP 128
#define PITCH 132
#define TOTAL_PTS (NB * NPTS)

// Scratch (no cudaMalloc allowed)
__device__ float g_code[DEPTH][NB][HID];
__device__ float g_norm[5][6];  // [|m|][shift]

// ---------------------------------------------------------------------------
// Prep: per-(layer, batch) code vectors  +  Legendre normalization table
// ---------------------------------------------------------------------------
__global__ void prep_kernel(const float* __restrict__ a,
                            const float* __restrict__ Wcode,
                            const float* __restrict__ bcode) {
    int blk = blockIdx.x;          // layer*8 + b
    int layer = blk >> 3;
    int b = blk & 7;
    int h = threadIdx.x;           // 0..127
    const float* wc = Wcode + (layer * HID + h) * CODE_D;
    const float* av = a + b * CODE_D;
    float s = 0.f;
    #pragma unroll 4
    for (int c = 0; c < CODE_D; ++c) s = fmaf(av[c], wc[c], s);
    g_code[layer][b][h] = s + bcode[layer * HID + h];

    if (blk == 0 && h < 30) {
        int am = h / 6, sh = h % 6, l = am + sh;
        double r = 1.0;
        for (int k = l - am + 1; k <= l + am; ++k) r /= (double)k;
        g_norm[am][sh] = (float)sqrt((2.0 * l + 1.0) / (4.0 * M_PI) * r);
    }
}

// ---------------------------------------------------------------------------
// Main fused kernel: 1 block = 128 points, 256 threads
// ---------------------------------------------------------------------------
__global__ __launch_bounds__(256, 1)
void sinr_kernel(const float* __restrict__ x,
                 const float* __restrict__ Wftr,
                 const float* __restrict__ bftr,
                 const float* __restrict__ Wfwd,
                 const float* __restrict__ bfwd,
                 const float* __restrict__ Wout,
                 const float* __restrict__ bout,
                 float* __restrict__ out) {
    extern __shared__ float sm[];
    float* zs  = sm;                        // TP * PITCH
    float* Ws  = zs + TP * PITCH;           // HID * PITCH
    float* Ys  = Ws + HID * PITCH;          // 6 * TP * NFREQ
    float* Wfs = Ys + 6 * TP * NFREQ;       // 6 * HID * NFREQ
    float* bfs = Wfs + 6 * HID * NFREQ;     // 6 * HID

    const int tid = threadIdx.x;
    const int blk = blockIdx.x;
    const int pt0 = blk * TP;
    const int b = pt0 / NPTS;               // all points in a block share batch

    // ---- stage Wftr / bftr / Wfwd[0] into shared ----
    for (int i = tid; i < 6 * HID * NFREQ; i += 256) Wfs[i] = Wftr[i];
    for (int i = tid; i < 6 * HID; i += 256) bfs[i] = bftr[i];
    {
        const float4* src = (const float4*)Wfwd;
        for (int idx = tid; idx < HID * HID / 4; idx += 256) {
            int g = idx >> 5, h4 = idx & 31;
            *(float4*)&Ws[g * PITCH + h4 * 4] = src[idx];
        }
    }

    // ---- spherical harmonics: one point per thread (tid < 128) ----
    if (tid < TP) {
        float theta = x[(pt0 + tid) * 2 + 0];
        float phi   = x[(pt0 + tid) * 2 + 1];
        float c = cosf(phi);
        float s2 = sqrtf(fmaxf(1.f - c * c, 0.f));

        float P[5][6];   // [am][shift], l = am + shift
        float pmm = 1.f;
        #pragma unroll
        for (int am = 0; am < 5; ++am) {
            if (am > 0) pmm *= -(2.f * am - 1.f) * s2;
            float p0 = pmm;
            P[am][0] = p0;
            float p1 = c * (2.f * am + 1.f) * pmm;
            P[am][1] = p1;
            #pragma unroll
            for (int sh = 2; sh < 6; ++sh) {
                int l = am + sh;
                float pl = ((2.f * l - 1.f) * c * p1 - (l + am - 1.f) * p0) * (1.f / (float)sh);
                p0 = p1; p1 = pl;
                P[am][sh] = pl;
            }
        }
        float ck[5], sk[5];
        float c1, s1;
        sincosf(theta, &s1, &c1);
        ck[0] = 1.f; sk[0] = 0.f;
        ck[1] = c1;  sk[1] = s1;
        #pragma unroll
        for (int m = 2; m < 5; ++m) {
            ck[m] = c1 * ck[m - 1] - s1 * sk[m - 1];
            sk[m] = s1 * ck[m - 1] + c1 * sk[m - 1];
        }
        const float SQ2 = 1.41421356237309515f;
        #pragma unroll
        for (int s = 0; s < 6; ++s) {
            float* yrow = &Ys[(s * TP + tid) * NFREQ];
            yrow[4] = g_norm[0][s] * P[0][s];
            #pragma unroll
            for (int am = 1; am < 5; ++am) {
                float base = SQ2 * g_norm[am][s] * P[am][s];
                if (am & 1) base = -base;
                yrow[4 + am] = base * ck[am];   // m > 0: cos
                yrow[4 - am] = base * sk[am];   // m < 0: sin
            }
        }
    }
    __syncthreads();

    // ---- register tile mapping: warp grid 4(p) x 2(g); lane = pg*8 + gg ----
    const int warp = tid >> 5, lane = tid & 31;
    const int pg = lane >> 3, gg = lane & 7;
    const int warpP = warp & 3, warpG = warp >> 2;
    const int pb = warpP * 32 + pg;   // p = pb + 4*j,  j = 0..7
    const int gb = warpG * 64 + gg;   // g = gb + 8*i,  i = 0..7

    // ---- feat_0 -> zs ----
    {
        float wfreg[72], bfr[8];
        #pragma unroll
        for (int i8 = 0; i8 < 8; ++i8) {
            int g = gb + 8 * i8;
            bfr[i8] = bfs[g];
            #pragma unroll
            for (int f = 0; f < 9; ++f) wfreg[i8 * 9 + f] = Wfs[g * 9 + f];
        }
        #pragma unroll
        for (int j = 0; j < 8; ++j) {
            int p = pb + 4 * j;
            float y[9];
            #pragma unroll
            for (int f = 0; f < 9; ++f) y[f] = Ys[p * NFREQ + f];
            #pragma unroll
            for (int i8 = 0; i8 < 8; ++i8) {
                float v = bfr[i8];
                #pragma unroll
                for (int f = 0; f < 9; ++f) v = fmaf(y[f], wfreg[i8 * 9 + f], v);
                zs[p * PITCH + gb + 8 * i8] = v;
            }
        }
    }
    __syncthreads();

    // ---- 5 dense layers, fully fused ----
    for (int layer = 0; layer < DEPTH; ++layer) {
        float acc[8][8];
        #pragma unroll
        for (int j = 0; j < 8; ++j)
            #pragma unroll
            for (int i8 = 0; i8 < 8; ++i8) acc[j][i8] = 0.f;

        #pragma unroll 2
        for (int k = 0; k < HID; k += 4) {
            float4 zv[8], wv[8];
            #pragma unroll
            for (int j = 0; j < 8; ++j)
                zv[j] = *(const float4*)&zs[(pb + 4 * j) * PITCH + k];
            #pragma unroll
            for (int i8 = 0; i8 < 8; ++i8)
                wv[i8] = *(const float4*)&Ws[(gb + 8 * i8) * PITCH + k];
            #pragma unroll
            for (int j = 0; j < 8; ++j)
                #pragma unroll
                for (int i8 = 0; i8 < 8; ++i8) {
                    acc[j][i8] = fmaf(zv[j].x, wv[i8].x, acc[j][i8]);
                    acc[j][i8] = fmaf(zv[j].y, wv[i8].y, acc[j][i8]);
                    acc[j][i8] = fmaf(zv[j].z, wv[i8].z, acc[j][i8]);
                    acc[j][i8] = fmaf(zv[j].w, wv[i8].w, acc[j][i8]);
                }
        }

        // epilogue: + bfwd + code, then * feat_{layer+1}
        {
            const int s = layer + 1;
            float cb[8], bfr[8], wfreg[72];
            #pragma unroll
            for (int i8 = 0; i8 < 8; ++i8) {
                int g = gb + 8 * i8;
                cb[i8]  = g_code[layer][b][g] + bfwd[layer * HID + g];
                bfr[i8] = bfs[s * HID + g];
                #pragma unroll
                for (int f = 0; f < 9; ++f)
                    wfreg[i8 * 9 + f] = Wfs[(s * HID + g) * 9 + f];
            }
            #pragma unroll
            for (int j = 0; j < 8; ++j) {
                int p = pb + 4 * j;
                float y[9];
                #pragma unroll
                for (int f = 0; f < 9; ++f) y[f] = Ys[(s * TP + p) * NFREQ + f];
                #pragma unroll
                for (int i8 = 0; i8 < 8; ++i8) {
                    float feat = bfr[i8];
                    #pragma unroll
                    for (int f = 0; f < 9; ++f)
                        feat = fmaf(y[f], wfreg[i8 * 9 + f], feat);
                    acc[j][i8] = (acc[j][i8] + cb[i8]) * feat;
                }
            }
        }

        __syncthreads();   // all warps done reading zs/Ws

        // write back z, stage next layer's W
        #pragma unroll
        for (int j = 0; j < 8; ++j)
            #pragma unroll
            for (int i8 = 0; i8 < 8; ++i8)
                zs[(pb + 4 * j) * PITCH + gb + 8 * i8] = acc[j][i8];

        if (layer + 1 < DEPTH) {
            const float4* src = (const float4*)(Wfwd + (size_t)(layer + 1) * HID * HID);
            for (int idx = tid; idx < HID * HID / 4; idx += 256) {
                int g = idx >> 5, h4 = idx & 31;
                *(float4*)&Ws[g * PITCH + h4 * 4] = src[idx];
            }
        }
        __syncthreads();
    }

    // ---- output: out[p] = z[p] . Wout + bout ----
    {
        float wreg[4];
        #pragma unroll
        for (int u = 0; u < 4; ++u) wreg[u] = Wout[lane * 4 + u];
        float bo = *bout;
        for (int r = 0; r < 16; ++r) {
            int p = warp * 16 + r;
            float4 zv = *(const float4*)&zs[p * PITCH + lane * 4];
            float v = zv.x * wreg[0] + zv.y * wreg[1] + zv.z * wreg[2] + zv.w * wreg[3];
            #pragma unroll
            for (int o = 16; o > 0; o >>= 1) v += __shfl_xor_sync(0xffffffffu, v, o);
            if (lane == 0) out[pt0 + p] = v + bo;
        }
    }
}

// ---------------------------------------------------------------------------
extern "C" void kernel_launch(void* const* d_in, const int* in_sizes, int n_in,
                              void* d_out, int out_size) {
    const float* x     = (const float*)d_in[0];
    const float* a     = (const float*)d_in[1];
    const float* Wftr  = (const float*)d_in[2];
    const float* bftr  = (const float*)d_in[3];
    const float* Wfwd  = (const float*)d_in[4];
    const float* bfwd  = (const float*)d_in[5];
    const float* Wcode = (const float*)d_in[6];
    const float* bcode = (const float*)d_in[7];
    const float* Wout  = (const float*)d_in[8];
    const float* bout  = (const float*)d_in[9];
    float* out = (float*)d_out;

    prep_kernel<<<DEPTH * NB, HID>>>(a, Wcode, bcode);

    size_t smem = (size_t)(TP * PITCH + HID * PITCH + 6 * TP * NFREQ +
                           6 * HID * NFREQ + 6 * HID) * sizeof(float);
    cudaFuncSetAttribute(sinr_kernel, cudaFuncAttributeMaxDynamicSharedMemorySize,
                         (int)smem);
    sinr_kernel<<<TOTAL_PTS / TP, 256, smem>>>(x, Wftr, bftr, Wfwd, bfwd,
                                               Wout, bout, out);

    // second tuple element: x passthrough
    if (out_size >= TOTAL_PTS + in_sizes[0]) {
        cudaMemcpyAsync(out + TOTAL_PTS, x, (size_t)in_sizes[0] * sizeof(float),
                        cudaMemcpyDeviceToDevice);
    }
}

// round 6
// speedup vs baseline: 1.8844x; 1.8844x over previous
#include <cuda_runtime.h>
#include <cuda_bf16.h>
#include <math.h>
#include <stdint.h>

#ifndef M_PI
#define M_PI 3.14159265358979323846
#endif

#define DEPTH 5
#define HID 128
#define CODE_D 400
#define NFREQ 9
#define NB 8
#define NPTS 32768
#define TP 128
#define TOTAL_PTS (NB * NPTS)

#define PZ 136   // bf16 pitch for 128-col tiles (Z, W)
#define PY 24    // bf16 pitch for 16-col tiles (Y, F)

// ---------------------------------------------------------------------------
// Device scratch (no cudaMalloc allowed)
// ---------------------------------------------------------------------------
__device__ float g_code[DEPTH][NB][HID];
__device__ float g_norm[5][6];
__device__ __align__(16) __nv_bfloat16 g_wt[DEPTH][2][HID * PZ];      // hi/lo
__device__ __align__(16) __nv_bfloat16 g_ft[DEPTH + 1][2][HID * PY];  // hi/lo

// ---------------------------------------------------------------------------
// SMEM byte map
// ---------------------------------------------------------------------------
#define SM_CB    0
#define SM_FB    512
#define SM_WOUT  1024
#define SM_OUTP  1536                 // float[2][128]
#define SM_YS    2560                 // 6*128*9 f32 = 27648
#define SM_ZH    30208                // 128*136*2 = 34816
#define SM_ZL    65024
#define SM_WH    99840
#define SM_WL    134656
#define SM_YH    169472               // 128*24*2 = 6144
#define SM_YL    175616
#define SM_FH    181760
#define SM_FL    187904
#define SM_TOTAL 194048

// ---------------------------------------------------------------------------
// PTX helpers (baseline ISA only: ldmatrix + mma.sync, both fine on sm_103)
// ---------------------------------------------------------------------------
__device__ __forceinline__ uint32_t smem_u32(const void* p) {
    uint32_t a;
    asm("{ .reg .u64 t; cvta.to.shared.u64 t, %1; cvt.u32.u64 %0, t; }"
        : "=r"(a) : "l"(p));
    return a;
}
__device__ __forceinline__ void ldsm4(uint32_t* r, uint32_t addr) {
    asm volatile("ldmatrix.sync.aligned.m8n8.x4.shared.b16 {%0,%1,%2,%3}, [%4];"
                 : "=r"(r[0]), "=r"(r[1]), "=r"(r[2]), "=r"(r[3]) : "r"(addr));
}
__device__ __forceinline__ void ldsm2(uint32_t* r, uint32_t addr) {
    asm volatile("ldmatrix.sync.aligned.m8n8.x2.shared.b16 {%0,%1}, [%2];"
                 : "=r"(r[0]), "=r"(r[1]) : "r"(addr));
}
__device__ __forceinline__ void mma16816(float* d, const uint32_t* a, const uint32_t* b) {
    asm volatile(
        "mma.sync.aligned.m16n8k16.row.col.f32.bf16.bf16.f32 "
        "{%0,%1,%2,%3}, {%4,%5,%6,%7}, {%8,%9}, {%0,%1,%2,%3};"
        : "+f"(d[0]), "+f"(d[1]), "+f"(d[2]), "+f"(d[3])
        : "r"(a[0]), "r"(a[1]), "r"(a[2]), "r"(a[3]), "r"(b[0]), "r"(b[1]));
}
__device__ __forceinline__ void split2(float z0, float z1, uint32_t& hi, uint32_t& lo) {
    __nv_bfloat16 h0 = __float2bfloat16(z0);
    __nv_bfloat16 h1 = __float2bfloat16(z1);
    __nv_bfloat16 l0 = __float2bfloat16(z0 - __bfloat162float(h0));
    __nv_bfloat16 l1 = __float2bfloat16(z1 - __bfloat162float(h1));
    hi = (uint32_t)__bfloat16_as_ushort(h0) | ((uint32_t)__bfloat16_as_ushort(h1) << 16);
    lo = (uint32_t)__bfloat16_as_ushort(l0) | ((uint32_t)__bfloat16_as_ushort(l1) << 16);
}

// ---------------------------------------------------------------------------
// Prep 1: code vectors + Legendre norm table
// ---------------------------------------------------------------------------
__global__ void prep_code(const float* __restrict__ a,
                          const float* __restrict__ Wcode,
                          const float* __restrict__ bcode) {
    int blk = blockIdx.x, layer = blk >> 3, b = blk & 7, h = threadIdx.x;
    const float* wc = Wcode + (layer * HID + h) * CODE_D;
    const float* av = a + b * CODE_D;
    float s = 0.f;
    #pragma unroll 4
    for (int c = 0; c < CODE_D; ++c) s = fmaf(av[c], wc[c], s);
    g_code[layer][b][h] = s + bcode[layer * HID + h];

    if (blk == 0 && h < 30) {
        int am = h / 6, sh = h % 6, l = am + sh;
        double r = 1.0;
        for (int k = l - am + 1; k <= l + am; ++k) r /= (double)k;
        g_norm[am][sh] = (float)sqrt((2.0 * l + 1.0) / (4.0 * M_PI) * r);
    }
}

// ---------------------------------------------------------------------------
// Prep 2: split fp32 weights -> bf16 hi/lo, padded pitched layout
// ---------------------------------------------------------------------------
#define WT_ELEMS (DEPTH * HID * PZ)        // 87040
#define FT_ELEMS ((DEPTH + 1) * HID * PY)  // 18432
__global__ void prep_w(const float* __restrict__ Wfwd,
                       const float* __restrict__ Wftr) {
    int i = blockIdx.x * 256 + threadIdx.x;
    if (i < WT_ELEMS) {
        int l = i / (HID * PZ), r = i % (HID * PZ), g = r / PZ, c = r % PZ;
        float v = (c < HID) ? Wfwd[(l * HID + g) * HID + c] : 0.f;
        __nv_bfloat16 hi = __float2bfloat16(v);
        __nv_bfloat16 lo = __float2bfloat16(v - __bfloat162float(hi));
        g_wt[l][0][r] = hi;
        g_wt[l][1][r] = lo;
    } else if (i < WT_ELEMS + FT_ELEMS) {
        int j = i - WT_ELEMS;
        int s = j / (HID * PY), r = j % (HID * PY), h = r / PY, f = r % PY;
        float v = (f < NFREQ) ? Wftr[(s * HID + h) * NFREQ + f] : 0.f;
        __nv_bfloat16 hi = __float2bfloat16(v);
        __nv_bfloat16 lo = __float2bfloat16(v - __bfloat162float(hi));
        g_ft[s][0][r] = hi;
        g_ft[s][1][r] = lo;
    }
}

// ---------------------------------------------------------------------------
// Main kernel: 1 block = 128 points, 256 threads, mma.sync bf16 split
// ---------------------------------------------------------------------------
__global__ __launch_bounds__(256, 1)
void sinr_mma(const float* __restrict__ x,
              const float* __restrict__ bftr,
              const float* __restrict__ bfwd,
              const float* __restrict__ Wout,
              const float* __restrict__ bout,
              float* __restrict__ out) {
    extern __shared__ char smem[];
    const uint32_t sb = smem_u32(smem);
    const int tid = threadIdx.x, wid = tid >> 5, lane = tid & 31;
    const int blk = blockIdx.x, pt0 = blk * TP, b = blk >> 8;

    const int warpP = wid & 3, warpG = wid >> 2;
    const int m0w = warpP * 32, n0w = warpG * 64;

    // ---- spherical harmonics into Ys (fp32), one point per thread ----
    if (tid < TP) {
        float theta = x[(pt0 + tid) * 2 + 0];
        float phi   = x[(pt0 + tid) * 2 + 1];
        float c = cosf(phi);
        float s2 = sqrtf(fmaxf(1.f - c * c, 0.f));
        float P[5][6];
        float pmm = 1.f;
        #pragma unroll
        for (int am = 0; am < 5; ++am) {
            if (am > 0) pmm *= -(2.f * am - 1.f) * s2;
            float p0 = pmm;
            P[am][0] = p0;
            float p1 = c * (2.f * am + 1.f) * pmm;
            P[am][1] = p1;
            #pragma unroll
            for (int sh = 2; sh < 6; ++sh) {
                int l = am + sh;
                float pl = ((2.f * l - 1.f) * c * p1 - (l + am - 1.f) * p0) * (1.f / (float)sh);
                p0 = p1; p1 = pl;
                P[am][sh] = pl;
            }
        }
        float ck[5], sk[5], c1, s1;
        sincosf(theta, &s1, &c1);
        ck[0] = 1.f; sk[0] = 0.f;
        ck[1] = c1;  sk[1] = s1;
        #pragma unroll
        for (int m = 2; m < 5; ++m) {
            ck[m] = c1 * ck[m - 1] - s1 * sk[m - 1];
            sk[m] = s1 * ck[m - 1] + c1 * sk[m - 1];
        }
        const float SQ2 = 1.41421356237309515f;
        float* Ys = (float*)(smem + SM_YS);
        #pragma unroll
        for (int s = 0; s < 6; ++s) {
            float* yrow = &Ys[(s * TP + tid) * NFREQ];
            yrow[4] = g_norm[0][s] * P[0][s];
            #pragma unroll
            for (int am = 1; am < 5; ++am) {
                float base = SQ2 * g_norm[am][s] * P[am][s];
                if (am & 1) base = -base;
                yrow[4 + am] = base * ck[am];
                yrow[4 - am] = base * sk[am];
            }
        }
    }

    // ---- init staging: F0, fb0, wout, outp; zero Y pad; split Y0 ----
    {
        const uint4* fs = (const uint4*)g_ft[0];
        uint4* fd = (uint4*)(smem + SM_FH);      // FH,FL contiguous (12288B)
        for (int i = tid; i < 768; i += 256) fd[i] = fs[i];
        if (tid < TP) {
            ((float*)(smem + SM_FB))[tid] = bftr[tid];
            ((float*)(smem + SM_WOUT))[tid] = Wout[tid];
            ((float*)(smem + SM_OUTP))[tid] = 0.f;
            ((float*)(smem + SM_OUTP))[TP + tid] = 0.f;
            // split own Y row for shift 0, zero pad cols 9..15
            const float* yr = (const float*)(smem + SM_YS) + tid * NFREQ;
            __nv_bfloat16* yh = (__nv_bfloat16*)(smem + SM_YH) + tid * PY;
            __nv_bfloat16* yl = (__nv_bfloat16*)(smem + SM_YL) + tid * PY;
            #pragma unroll
            for (int f = 0; f < NFREQ; ++f) {
                float v = yr[f];
                __nv_bfloat16 h = __float2bfloat16(v);
                yh[f] = h;
                yl[f] = __float2bfloat16(v - __bfloat162float(h));
            }
            #pragma unroll
            for (int f = NFREQ; f < 16; ++f) { yh[f] = __float2bfloat16(0.f); yl[f] = __float2bfloat16(0.f); }
        }
    }
    __syncthreads();

    // ldmatrix lane address components
    const uint32_t aRow = (uint32_t)(lane & 15);            // A-side row within tile pair
    const uint32_t aK8  = (uint32_t)((lane >> 4) * 8);      // A-side k half
    const uint32_t bRow = (uint32_t)((lane & 7) + ((lane >> 4) & 1) * 8);  // B x4 n row
    const uint32_t bK8  = (uint32_t)(((lane >> 3) & 1) * 8);               // B x4 k half
    const uint32_t fRow = (uint32_t)(lane & 7);             // F x2 n row
    const uint32_t fK8  = (uint32_t)(((lane >> 3) & 1) * 8);

    const float* cb  = (const float*)(smem + SM_CB);
    const float* fb  = (const float*)(smem + SM_FB);
    const float* wos = (const float*)(smem + SM_WOUT);

    const int eRow = lane >> 2;          // epilogue row within m-tile (d0/d1)
    const int eCol = (lane & 3) * 2;     // epilogue col pair offset

    // ---- init: z0 = Y0*Wftr0^T + bftr0 (feature mma only) ----
    {
        uint32_t Yh[2][4], Yl[2][4];
        #pragma unroll
        for (int mt = 0; mt < 2; ++mt) {
            uint32_t ro = ((uint32_t)(m0w + mt * 16) + aRow) * (PY * 2) + aK8 * 2;
            ldsm4(Yh[mt], sb + SM_YH + ro);
            ldsm4(Yl[mt], sb + SM_YL + ro);
        }
        #pragma unroll
        for (int nt = 0; nt < 8; ++nt) {
            int n0 = n0w + nt * 8;
            uint32_t Fh[2], Fl[2];
            uint32_t fo = ((uint32_t)n0 + fRow) * (PY * 2) + fK8 * 2;
            ldsm2(Fh, sb + SM_FH + fo);
            ldsm2(Fl, sb + SM_FL + fo);
            #pragma unroll
            for (int mt = 0; mt < 2; ++mt) {
                float fa[4] = {0.f, 0.f, 0.f, 0.f};
                mma16816(fa, Yh[mt], Fh);
                mma16816(fa, Yh[mt], Fl);
                mma16816(fa, Yl[mt], Fh);
                int c0 = n0 + eCol;
                float2 fbv = *(const float2*)&fb[c0];
                float z0 = fa[0] + fbv.x, z1 = fa[1] + fbv.y;
                float z2 = fa[2] + fbv.x, z3 = fa[3] + fbv.y;
                uint32_t hi, lo;
                int r0 = m0w + mt * 16 + eRow;
                uint32_t o0 = (uint32_t)(r0 * (PZ * 2) + c0 * 2);
                uint32_t o1 = o0 + 8 * (PZ * 2);
                split2(z0, z1, hi, lo);
                *(uint32_t*)(smem + SM_ZH + o0) = hi;
                *(uint32_t*)(smem + SM_ZL + o0) = lo;
                split2(z2, z3, hi, lo);
                *(uint32_t*)(smem + SM_ZH + o1) = hi;
                *(uint32_t*)(smem + SM_ZL + o1) = lo;
            }
        }
    }

    float os[4] = {0.f, 0.f, 0.f, 0.f};

    // =========================== 5 fused layers =============================
    for (int l = 0; l < DEPTH; ++l) {
        // ---- stage W[l] (hi+lo), F[l+1], biases, Y[l+1] split ----
        {
            const uint4* ws = (const uint4*)g_wt[l];
            uint4* wd = (uint4*)(smem + SM_WH);   // WH,WL contiguous (69632B)
            for (int i = tid; i < 4352; i += 256) wd[i] = ws[i];
            const uint4* fs = (const uint4*)g_ft[l + 1];
            uint4* fd = (uint4*)(smem + SM_FH);
            for (int i = tid; i < 768; i += 256) fd[i] = fs[i];
            if (tid < TP) {
                ((float*)(smem + SM_FB))[tid] = bftr[(l + 1) * HID + tid];
                ((float*)(smem + SM_CB))[tid] = g_code[l][b][tid] + bfwd[l * HID + tid];
                const float* yr = (const float*)(smem + SM_YS) + ((l + 1) * TP + tid) * NFREQ;
                __nv_bfloat16* yh = (__nv_bfloat16*)(smem + SM_YH) + tid * PY;
                __nv_bfloat16* yl = (__nv_bfloat16*)(smem + SM_YL) + tid * PY;
                #pragma unroll
                for (int f = 0; f < NFREQ; ++f) {
                    float v = yr[f];
                    __nv_bfloat16 h = __float2bfloat16(v);
                    yh[f] = h;
                    yl[f] = __float2bfloat16(v - __bfloat162float(h));
                }
            }
        }
        __syncthreads();

        // ---- main GEMM: acc = Z * W^T (split 3-term) ----
        float acc[2][8][4];
        #pragma unroll
        for (int mt = 0; mt < 2; ++mt)
            #pragma unroll
            for (int nt = 0; nt < 8; ++nt)
                #pragma unroll
                for (int r = 0; r < 4; ++r) acc[mt][nt][r] = 0.f;

        #pragma unroll
        for (int ks = 0; ks < 8; ++ks) {
            const uint32_t k0 = ks * 16;
            uint32_t Ah[2][4], Al[2][4];
            #pragma unroll
            for (int mt = 0; mt < 2; ++mt) {
                uint32_t ro = ((uint32_t)(m0w + mt * 16) + aRow) * (PZ * 2) + (k0 + aK8) * 2;
                ldsm4(Ah[mt], sb + SM_ZH + ro);
                ldsm4(Al[mt], sb + SM_ZL + ro);
            }
            uint32_t Bh[8][2], Bl[8][2];
            #pragma unroll
            for (int np = 0; np < 4; ++np) {
                uint32_t ro = ((uint32_t)(n0w + np * 16) + bRow) * (PZ * 2) + (k0 + bK8) * 2;
                uint32_t t[4];
                ldsm4(t, sb + SM_WH + ro);
                Bh[np * 2][0] = t[0]; Bh[np * 2][1] = t[1];
                Bh[np * 2 + 1][0] = t[2]; Bh[np * 2 + 1][1] = t[3];
                ldsm4(t, sb + SM_WL + ro);
                Bl[np * 2][0] = t[0]; Bl[np * 2][1] = t[1];
                Bl[np * 2 + 1][0] = t[2]; Bl[np * 2 + 1][1] = t[3];
            }
            #pragma unroll
            for (int mt = 0; mt < 2; ++mt)
                #pragma unroll
                for (int nt = 0; nt < 8; ++nt) {
                    mma16816(acc[mt][nt], Ah[mt], Bh[nt]);
                    mma16816(acc[mt][nt], Ah[mt], Bl[nt]);
                    mma16816(acc[mt][nt], Al[mt], Bh[nt]);
                }
        }

        // ---- epilogue: feat mma + combine + writeback / output ----
        {
            uint32_t Yh[2][4], Yl[2][4];
            #pragma unroll
            for (int mt = 0; mt < 2; ++mt) {
                uint32_t ro = ((uint32_t)(m0w + mt * 16) + aRow) * (PY * 2) + aK8 * 2;
                ldsm4(Yh[mt], sb + SM_YH + ro);
                ldsm4(Yl[mt], sb + SM_YL + ro);
            }
            #pragma unroll
            for (int nt = 0; nt < 8; ++nt) {
                int n0 = n0w + nt * 8;
                uint32_t Fh[2], Fl[2];
                uint32_t fo = ((uint32_t)n0 + fRow) * (PY * 2) + fK8 * 2;
                ldsm2(Fh, sb + SM_FH + fo);
                ldsm2(Fl, sb + SM_FL + fo);
                int c0 = n0 + eCol;
                float2 fbv = *(const float2*)&fb[c0];
                float2 cbv = *(const float2*)&cb[c0];
                #pragma unroll
                for (int mt = 0; mt < 2; ++mt) {
                    float fa[4] = {0.f, 0.f, 0.f, 0.f};
                    mma16816(fa, Yh[mt], Fh);
                    mma16816(fa, Yh[mt], Fl);
                    mma16816(fa, Yl[mt], Fh);
                    float z0 = (acc[mt][nt][0] + cbv.x) * (fa[0] + fbv.x);
                    float z1 = (acc[mt][nt][1] + cbv.y) * (fa[1] + fbv.y);
                    float z2 = (acc[mt][nt][2] + cbv.x) * (fa[2] + fbv.x);
                    float z3 = (acc[mt][nt][3] + cbv.y) * (fa[3] + fbv.y);
                    if (l < DEPTH - 1) {
                        uint32_t hi, lo;
                        int r0 = m0w + mt * 16 + eRow;
                        uint32_t o0 = (uint32_t)(r0 * (PZ * 2) + c0 * 2);
                        uint32_t o1 = o0 + 8 * (PZ * 2);
                        split2(z0, z1, hi, lo);
                        *(uint32_t*)(smem + SM_ZH + o0) = hi;
                        *(uint32_t*)(smem + SM_ZL + o0) = lo;
                        split2(z2, z3, hi, lo);
                        *(uint32_t*)(smem + SM_ZH + o1) = hi;
                        *(uint32_t*)(smem + SM_ZL + o1) = lo;
                    } else {
                        float2 wv = *(const float2*)&wos[c0];
                        os[mt * 2 + 0] = fmaf(z0, wv.x, fmaf(z1, wv.y, os[mt * 2 + 0]));
                        os[mt * 2 + 1] = fmaf(z2, wv.x, fmaf(z3, wv.y, os[mt * 2 + 1]));
                    }
                }
            }
        }
        __syncthreads();
    }

    // ---- output reduce: sum over the 4-lane col groups, then warp halves ----
    {
        #pragma unroll
        for (int i = 0; i < 4; ++i) {
            os[i] += __shfl_xor_sync(0xffffffffu, os[i], 1);
            os[i] += __shfl_xor_sync(0xffffffffu, os[i], 2);
        }
        float* outp = (float*)(smem + SM_OUTP);
        if ((lane & 3) == 0) {
            #pragma unroll
            for (int mt = 0; mt < 2; ++mt)
                #pragma unroll
                for (int rh = 0; rh < 2; ++rh) {
                    int r = m0w + mt * 16 + rh * 8 + eRow;
                    outp[warpG * TP + r] = os[mt * 2 + rh];
                }
        }
        __syncthreads();
        if (tid < TP) out[pt0 + tid] = outp[tid] + outp[TP + tid] + *bout;
    }
}

// ---------------------------------------------------------------------------
extern "C" void kernel_launch(void* const* d_in, const int* in_sizes, int n_in,
                              void* d_out, int out_size) {
    const float* x     = (const float*)d_in[0];
    const float* a     = (const float*)d_in[1];
    const float* Wftr  = (const float*)d_in[2];
    const float* bftr  = (const float*)d_in[3];
    const float* Wfwd  = (const float*)d_in[4];
    const float* bfwd  = (const float*)d_in[5];
    const float* Wcode = (const float*)d_in[6];
    const float* bcode = (const float*)d_in[7];
    const float* Wout  = (const float*)d_in[8];
    const float* bout  = (const float*)d_in[9];
    float* out = (float*)d_out;

    prep_code<<<DEPTH * NB, HID>>>(a, Wcode, bcode);
    prep_w<<<(WT_ELEMS + FT_ELEMS + 255) / 256, 256>>>(Wfwd, Wftr);

    cudaFuncSetAttribute(sinr_mma, cudaFuncAttributeMaxDynamicSharedMemorySize,
                         SM_TOTAL);
    sinr_mma<<<TOTAL_PTS / TP, 256, SM_TOTAL>>>(x, bftr, bfwd, Wout, bout, out);

    if (out_size >= TOTAL_PTS + in_sizes[0]) {
        cudaMemcpyAsync(out + TOTAL_PTS, x, (size_t)in_sizes[0] * sizeof(float),
                        cudaMemcpyDeviceToDevice);
    }
}

// round 7
// speedup vs baseline: 2.3415x; 1.2426x over previous
#include <cuda_runtime.h>
#include <cuda_bf16.h>
#include <math.h>
#include <stdint.h>

#ifndef M_PI
#define M_PI 3.14159265358979323846
#endif

#define DEPTH 5
#define HID 128
#define CODE_D 400
#define NFREQ 9
#define NB 8
#define NPTS 32768
#define TP 128
#define TOTAL_PTS (NB * NPTS)

#define PZ 136   // bf16 pitch for 128-col tiles (Z, W)
#define PY 24    // bf16 pitch for 16-col tiles (Y, F)

// ---------------------------------------------------------------------------
// Device scratch (no cudaMalloc allowed)
// ---------------------------------------------------------------------------
__device__ float g_code[DEPTH][NB][HID];
__device__ float g_norm[5][6];
__device__ __align__(16) __nv_bfloat16 g_wt[DEPTH][2][HID * PZ];      // hi/lo
__device__ __align__(16) __nv_bfloat16 g_ft[DEPTH + 1][2][HID * PY];  // hi/lo

// ---------------------------------------------------------------------------
// SMEM byte map
// ---------------------------------------------------------------------------
#define SM_CB    0
#define SM_FB    512
#define SM_WOUT  1024
#define SM_OUTP  1536                 // float[2][128]
#define SM_YS    2560                 // 6*128*9 f32 = 27648
#define SM_ZH    30208                // 128*136*2 = 34816
#define SM_ZL    65024
#define SM_WH    99840
#define SM_WL    134656
#define SM_YH    169472               // 128*24*2 = 6144
#define SM_YL    175616
#define SM_FH    181760
#define SM_FL    187904
#define SM_TOTAL 194048

// ---------------------------------------------------------------------------
// PTX helpers (baseline ISA: ldmatrix + mma.sync + cp.async, all ok on sm_103)
// ---------------------------------------------------------------------------
__device__ __forceinline__ uint32_t smem_u32(const void* p) {
    uint32_t a;
    asm("{ .reg .u64 t; cvta.to.shared.u64 t, %1; cvt.u32.u64 %0, t; }"
        : "=r"(a) : "l"(p));
    return a;
}
__device__ __forceinline__ void ldsm4(uint32_t* r, uint32_t addr) {
    asm volatile("ldmatrix.sync.aligned.m8n8.x4.shared.b16 {%0,%1,%2,%3}, [%4];"
                 : "=r"(r[0]), "=r"(r[1]), "=r"(r[2]), "=r"(r[3]) : "r"(addr));
}
__device__ __forceinline__ void ldsm2(uint32_t* r, uint32_t addr) {
    asm volatile("ldmatrix.sync.aligned.m8n8.x2.shared.b16 {%0,%1}, [%2];"
                 : "=r"(r[0]), "=r"(r[1]) : "r"(addr));
}
__device__ __forceinline__ void mma16816(float* d, const uint32_t* a, const uint32_t* b) {
    asm volatile(
        "mma.sync.aligned.m16n8k16.row.col.f32.bf16.bf16.f32 "
        "{%0,%1,%2,%3}, {%4,%5,%6,%7}, {%8,%9}, {%0,%1,%2,%3};"
        : "+f"(d[0]), "+f"(d[1]), "+f"(d[2]), "+f"(d[3])
        : "r"(a[0]), "r"(a[1]), "r"(a[2]), "r"(a[3]), "r"(b[0]), "r"(b[1]));
}
__device__ __forceinline__ void split2(float z0, float z1, uint32_t& hi, uint32_t& lo) {
    __nv_bfloat16 h0 = __float2bfloat16(z0);
    __nv_bfloat16 h1 = __float2bfloat16(z1);
    __nv_bfloat16 l0 = __float2bfloat16(z0 - __bfloat162float(h0));
    __nv_bfloat16 l1 = __float2bfloat16(z1 - __bfloat162float(h1));
    hi = (uint32_t)__bfloat16_as_ushort(h0) | ((uint32_t)__bfloat16_as_ushort(h1) << 16);
    lo = (uint32_t)__bfloat16_as_ushort(l0) | ((uint32_t)__bfloat16_as_ushort(l1) << 16);
}
__device__ __forceinline__ void cpa16(uint32_t dst, const void* src) {
    asm volatile("cp.async.cg.shared.global [%0], [%1], 16;" :: "r"(dst), "l"(src));
}
#define CP_COMMIT() asm volatile("cp.async.commit_group;" ::: "memory")
#define CP_WAIT(n)  asm volatile("cp.async.wait_group %0;" :: "n"(n) : "memory")

// ---------------------------------------------------------------------------
// Merged prep kernel:
//   blocks [0, NCODE_BLK): code vectors, one warp per (layer,b,h) dot
//   blocks [NCODE_BLK, ...): weight split/pad, 256 elems per block
// ---------------------------------------------------------------------------
#define NCODE_BLK (DEPTH * NB * HID / 8)       // 640 (8 warps/block)
#define WT_ELEMS (DEPTH * HID * PZ)            // 87040
#define FT_ELEMS ((DEPTH + 1) * HID * PY)      // 18432
#define NW_BLK ((WT_ELEMS + FT_ELEMS + 255) / 256)   // 412

__global__ void prep_all(const float* __restrict__ a,
                         const float* __restrict__ Wcode,
                         const float* __restrict__ bcode,
                         const float* __restrict__ Wfwd,
                         const float* __restrict__ Wftr) {
    int blk = blockIdx.x, tid = threadIdx.x;
    if (blk < NCODE_BLK) {
        int wid = tid >> 5, lane = tid & 31;
        int gw = blk * 8 + wid;                // 0..5119
        int layer = gw >> 10;                  // /1024
        int rem = gw & 1023;
        int b = rem >> 7, h = rem & 127;
        const float* wc = Wcode + (size_t)(layer * HID + h) * CODE_D;
        const float* av = a + b * CODE_D;
        float s = 0.f;
        for (int c = lane; c < CODE_D; c += 32) s = fmaf(av[c], wc[c], s);
        #pragma unroll
        for (int o = 16; o > 0; o >>= 1) s += __shfl_xor_sync(0xffffffffu, s, o);
        if (lane == 0) g_code[layer][b][h] = s + bcode[layer * HID + h];
        if (blk == 0 && wid == 0 && lane < 30) {
            int am = lane / 6, sh = lane % 6, l = am + sh;
            double r = 1.0;
            for (int k = l - am + 1; k <= l + am; ++k) r /= (double)k;
            g_norm[am][sh] = (float)sqrt((2.0 * l + 1.0) / (4.0 * M_PI) * r);
        }
    } else {
        int i = (blk - NCODE_BLK) * 256 + tid;
        if (i < WT_ELEMS) {
            int l = i / (HID * PZ), r = i % (HID * PZ), g = r / PZ, c = r % PZ;
            float v = (c < HID) ? Wfwd[(l * HID + g) * HID + c] : 0.f;
            __nv_bfloat16 hi = __float2bfloat16(v);
            __nv_bfloat16 lo = __float2bfloat16(v - __bfloat162float(hi));
            g_wt[l][0][r] = hi;
            g_wt[l][1][r] = lo;
        } else if (i < WT_ELEMS + FT_ELEMS) {
            int j = i - WT_ELEMS;
            int s = j / (HID * PY), r = j % (HID * PY), h = r / PY, f = r % PY;
            float v = (f < NFREQ) ? Wftr[(s * HID + h) * NFREQ + f] : 0.f;
            __nv_bfloat16 hi = __float2bfloat16(v);
            __nv_bfloat16 lo = __float2bfloat16(v - __bfloat162float(hi));
            g_ft[s][0][r] = hi;
            g_ft[s][1][r] = lo;
        }
    }
}

// ---------------------------------------------------------------------------
// Main kernel: 1 block = 128 points, 256 threads, mma.sync bf16 split,
// cp.async pipelined weight staging.
// ---------------------------------------------------------------------------
__global__ __launch_bounds__(256, 1)
void sinr_mma(const float* __restrict__ x,
              const float* __restrict__ bftr,
              const float* __restrict__ bfwd,
              const float* __restrict__ Wout,
              const float* __restrict__ bout,
              float* __restrict__ out) {
    extern __shared__ char smem[];
    const uint32_t sb = smem_u32(smem);
    const int tid = threadIdx.x, wid = tid >> 5, lane = tid & 31;
    const int blk = blockIdx.x, pt0 = blk * TP, b = blk >> 8;

    const int warpP = wid & 3, warpG = wid >> 2;
    const int m0w = warpP * 32, n0w = warpG * 64;

    // ---- issue F[0] group, then W[0] group (oldest-first wait discipline) ----
    {
        const char* fs = (const char*)g_ft[0];
        for (int i = tid; i < 768; i += 256)
            cpa16(sb + SM_FH + i * 16, fs + i * 16);
        CP_COMMIT();
        const char* ws = (const char*)g_wt[0];
        for (int i = tid; i < 4352; i += 256)
            cpa16(sb + SM_WH + i * 16, ws + i * 16);
        CP_COMMIT();
    }

    // ---- spherical harmonics into Ys (fp32), one point per thread ----
    if (tid < TP) {
        float theta = x[(pt0 + tid) * 2 + 0];
        float phi   = x[(pt0 + tid) * 2 + 1];
        float c = cosf(phi);
        float s2 = sqrtf(fmaxf(1.f - c * c, 0.f));
        float P[5][6];
        float pmm = 1.f;
        #pragma unroll
        for (int am = 0; am < 5; ++am) {
            if (am > 0) pmm *= -(2.f * am - 1.f) * s2;
            float p0 = pmm;
            P[am][0] = p0;
            float p1 = c * (2.f * am + 1.f) * pmm;
            P[am][1] = p1;
            #pragma unroll
            for (int sh = 2; sh < 6; ++sh) {
                int l = am + sh;
                float pl = ((2.f * l - 1.f) * c * p1 - (l + am - 1.f) * p0) * (1.f / (float)sh);
                p0 = p1; p1 = pl;
                P[am][sh] = pl;
            }
        }
        float ck[5], sk[5], c1, s1;
        sincosf(theta, &s1, &c1);
        ck[0] = 1.f; sk[0] = 0.f;
        ck[1] = c1;  sk[1] = s1;
        #pragma unroll
        for (int m = 2; m < 5; ++m) {
            ck[m] = c1 * ck[m - 1] - s1 * sk[m - 1];
            sk[m] = s1 * ck[m - 1] + c1 * sk[m - 1];
        }
        const float SQ2 = 1.41421356237309515f;
        float* Ys = (float*)(smem + SM_YS);
        #pragma unroll
        for (int s = 0; s < 6; ++s) {
            float* yrow = &Ys[(s * TP + tid) * NFREQ];
            yrow[4] = g_norm[0][s] * P[0][s];
            #pragma unroll
            for (int am = 1; am < 5; ++am) {
                float base = SQ2 * g_norm[am][s] * P[am][s];
                if (am & 1) base = -base;
                yrow[4 + am] = base * ck[am];
                yrow[4 - am] = base * sk[am];
            }
        }
    }

    // ---- init staging: fb0, wout, outp zero; split Y0 (+zero pad) ----
    if (tid < TP) {
        ((float*)(smem + SM_FB))[tid] = bftr[tid];
        ((float*)(smem + SM_WOUT))[tid] = Wout[tid];
        ((float*)(smem + SM_OUTP))[tid] = 0.f;
        ((float*)(smem + SM_OUTP))[TP + tid] = 0.f;
        const float* yr = (const float*)(smem + SM_YS) + tid * NFREQ;
        __nv_bfloat16* yh = (__nv_bfloat16*)(smem + SM_YH) + tid * PY;
        __nv_bfloat16* yl = (__nv_bfloat16*)(smem + SM_YL) + tid * PY;
        #pragma unroll
        for (int f = 0; f < NFREQ; ++f) {
            float v = yr[f];
            __nv_bfloat16 h = __float2bfloat16(v);
            yh[f] = h;
            yl[f] = __float2bfloat16(v - __bfloat162float(h));
        }
        #pragma unroll
        for (int f = NFREQ; f < 16; ++f) { yh[f] = __float2bfloat16(0.f); yl[f] = __float2bfloat16(0.f); }
    }
    CP_WAIT(1);        // F[0] landed (W[0] may still be in flight)
    __syncthreads();

    // ldmatrix lane address components
    const uint32_t aRow = (uint32_t)(lane & 15);
    const uint32_t aK8  = (uint32_t)((lane >> 4) * 8);
    const uint32_t bRow = (uint32_t)((lane & 7) + ((lane >> 4) & 1) * 8);
    const uint32_t bK8  = (uint32_t)(((lane >> 3) & 1) * 8);
    const uint32_t fRow = (uint32_t)(lane & 7);
    const uint32_t fK8  = (uint32_t)(((lane >> 3) & 1) * 8);

    const float* cb  = (const float*)(smem + SM_CB);
    const float* fb  = (const float*)(smem + SM_FB);
    const float* wos = (const float*)(smem + SM_WOUT);

    const int eRow = lane >> 2;
    const int eCol = (lane & 3) * 2;

    // ---- init: z0 = Y0*Wftr0^T + bftr0 (feature mma only) ----
    {
        uint32_t Yh[2][4], Yl[2][4];
        #pragma unroll
        for (int mt = 0; mt < 2; ++mt) {
            uint32_t ro = ((uint32_t)(m0w + mt * 16) + aRow) * (PY * 2) + aK8 * 2;
            ldsm4(Yh[mt], sb + SM_YH + ro);
            ldsm4(Yl[mt], sb + SM_YL + ro);
        }
        #pragma unroll
        for (int nt = 0; nt < 8; ++nt) {
            int n0 = n0w + nt * 8;
            uint32_t Fh[2], Fl[2];
            uint32_t fo = ((uint32_t)n0 + fRow) * (PY * 2) + fK8 * 2;
            ldsm2(Fh, sb + SM_FH + fo);
            ldsm2(Fl, sb + SM_FL + fo);
            #pragma unroll
            for (int mt = 0; mt < 2; ++mt) {
                float fa[4] = {0.f, 0.f, 0.f, 0.f};
                mma16816(fa, Yh[mt], Fh);
                mma16816(fa, Yh[mt], Fl);
                mma16816(fa, Yl[mt], Fh);
                int c0 = n0 + eCol;
                float2 fbv = *(const float2*)&fb[c0];
                float z0 = fa[0] + fbv.x, z1 = fa[1] + fbv.y;
                float z2 = fa[2] + fbv.x, z3 = fa[3] + fbv.y;
                uint32_t hi, lo;
                int r0 = m0w + mt * 16 + eRow;
                uint32_t o0 = (uint32_t)(r0 * (PZ * 2) + c0 * 2);
                uint32_t o1 = o0 + 8 * (PZ * 2);
                split2(z0, z1, hi, lo);
                *(uint32_t*)(smem + SM_ZH + o0) = hi;
                *(uint32_t*)(smem + SM_ZL + o0) = lo;
                split2(z2, z3, hi, lo);
                *(uint32_t*)(smem + SM_ZH + o1) = hi;
                *(uint32_t*)(smem + SM_ZL + o1) = lo;
            }
        }
    }
    __syncthreads();   // protect Y/F buffers before loop-top restaging

    float os[4] = {0.f, 0.f, 0.f, 0.f};

    // =========================== 5 fused layers =============================
    for (int l = 0; l < DEPTH; ++l) {
        // ---- issue F[l+1] cp.async; stage biases + Y[l+1] split ----
        {
            const char* fs = (const char*)g_ft[l + 1];
            for (int i = tid; i < 768; i += 256)
                cpa16(sb + SM_FH + i * 16, fs + i * 16);
            CP_COMMIT();
            if (tid < TP) {
                ((float*)(smem + SM_FB))[tid] = bftr[(l + 1) * HID + tid];
                ((float*)(smem + SM_CB))[tid] = g_code[l][b][tid] + bfwd[l * HID + tid];
                const float* yr = (const float*)(smem + SM_YS) + ((l + 1) * TP + tid) * NFREQ;
                __nv_bfloat16* yh = (__nv_bfloat16*)(smem + SM_YH) + tid * PY;
                __nv_bfloat16* yl = (__nv_bfloat16*)(smem + SM_YL) + tid * PY;
                #pragma unroll
                for (int f = 0; f < NFREQ; ++f) {
                    float v = yr[f];
                    __nv_bfloat16 h = __float2bfloat16(v);
                    yh[f] = h;
                    yl[f] = __float2bfloat16(v - __bfloat162float(h));
                }
            }
        }
        CP_WAIT(1);        // W[l] landed (F[l+1] still pending)
        __syncthreads();

        // ---- main GEMM: acc = Z * W^T (split 3-term) ----
        float acc[2][8][4];
        #pragma unroll
        for (int mt = 0; mt < 2; ++mt)
            #pragma unroll
            for (int nt = 0; nt < 8; ++nt)
                #pragma unroll
                for (int r = 0; r < 4; ++r) acc[mt][nt][r] = 0.f;

        #pragma unroll
        for (int ks = 0; ks < 8; ++ks) {
            const uint32_t k0 = ks * 16;
            uint32_t Ah[2][4], Al[2][4];
            #pragma unroll
            for (int mt = 0; mt < 2; ++mt) {
                uint32_t ro = ((uint32_t)(m0w + mt * 16) + aRow) * (PZ * 2) + (k0 + aK8) * 2;
                ldsm4(Ah[mt], sb + SM_ZH + ro);
                ldsm4(Al[mt], sb + SM_ZL + ro);
            }
            uint32_t Bh[8][2], Bl[8][2];
            #pragma unroll
            for (int np = 0; np < 4; ++np) {
                uint32_t ro = ((uint32_t)(n0w + np * 16) + bRow) * (PZ * 2) + (k0 + bK8) * 2;
                uint32_t t[4];
                ldsm4(t, sb + SM_WH + ro);
                Bh[np * 2][0] = t[0]; Bh[np * 2][1] = t[1];
                Bh[np * 2 + 1][0] = t[2]; Bh[np * 2 + 1][1] = t[3];
                ldsm4(t, sb + SM_WL + ro);
                Bl[np * 2][0] = t[0]; Bl[np * 2][1] = t[1];
                Bl[np * 2 + 1][0] = t[2]; Bl[np * 2 + 1][1] = t[3];
            }
            #pragma unroll
            for (int mt = 0; mt < 2; ++mt)
                #pragma unroll
                for (int nt = 0; nt < 8; ++nt) {
                    mma16816(acc[mt][nt], Ah[mt], Bh[nt]);
                    mma16816(acc[mt][nt], Ah[mt], Bl[nt]);
                    mma16816(acc[mt][nt], Al[mt], Bh[nt]);
                }
        }

        CP_WAIT(0);        // F[l+1] landed
        __syncthreads();   // all W reads done + F visible

        // ---- prefetch next layer's W while epilogue runs ----
        if (l + 1 < DEPTH) {
            const char* ws = (const char*)g_wt[l + 1];
            for (int i = tid; i < 4352; i += 256)
                cpa16(sb + SM_WH + i * 16, ws + i * 16);
        }
        CP_COMMIT();       // uniform commit (empty group ok on last layer)

        // ---- epilogue: feat mma + combine + writeback / output ----
        {
            uint32_t Yh[2][4], Yl[2][4];
            #pragma unroll
            for (int mt = 0; mt < 2; ++mt) {
                uint32_t ro = ((uint32_t)(m0w + mt * 16) + aRow) * (PY * 2) + aK8 * 2;
                ldsm4(Yh[mt], sb + SM_YH + ro);
                ldsm4(Yl[mt], sb + SM_YL + ro);
            }
            #pragma unroll
            for (int nt = 0; nt < 8; ++nt) {
                int n0 = n0w + nt * 8;
                uint32_t Fh[2], Fl[2];
                uint32_t fo = ((uint32_t)n0 + fRow) * (PY * 2) + fK8 * 2;
                ldsm2(Fh, sb + SM_FH + fo);
                ldsm2(Fl, sb + SM_FL + fo);
                int c0 = n0 + eCol;
                float2 fbv = *(const float2*)&fb[c0];
                float2 cbv = *(const float2*)&cb[c0];
                #pragma unroll
                for (int mt = 0; mt < 2; ++mt) {
                    float fa[4] = {0.f, 0.f, 0.f, 0.f};
                    mma16816(fa, Yh[mt], Fh);
                    mma16816(fa, Yh[mt], Fl);
                    mma16816(fa, Yl[mt], Fh);
                    float z0 = (acc[mt][nt][0] + cbv.x) * (fa[0] + fbv.x);
                    float z1 = (acc[mt][nt][1] + cbv.y) * (fa[1] + fbv.y);
                    float z2 = (acc[mt][nt][2] + cbv.x) * (fa[2] + fbv.x);
                    float z3 = (acc[mt][nt][3] + cbv.y) * (fa[3] + fbv.y);
                    if (l < DEPTH - 1) {
                        uint32_t hi, lo;
                        int r0 = m0w + mt * 16 + eRow;
                        uint32_t o0 = (uint32_t)(r0 * (PZ * 2) + c0 * 2);
                        uint32_t o1 = o0 + 8 * (PZ * 2);
                        split2(z0, z1, hi, lo);
                        *(uint32_t*)(smem + SM_ZH + o0) = hi;
                        *(uint32_t*)(smem + SM_ZL + o0) = lo;
                        split2(z2, z3, hi, lo);
                        *(uint32_t*)(smem + SM_ZH + o1) = hi;
                        *(uint32_t*)(smem + SM_ZL + o1) = lo;
                    } else {
                        float2 wv = *(const float2*)&wos[c0];
                        os[mt * 2 + 0] = fmaf(z0, wv.x, fmaf(z1, wv.y, os[mt * 2 + 0]));
                        os[mt * 2 + 1] = fmaf(z2, wv.x, fmaf(z3, wv.y, os[mt * 2 + 1]));
                    }
                }
            }
        }
        __syncthreads();   // epilogue F/Y/fb/cb reads + Z writes done
    }

    // ---- output reduce ----
    {
        #pragma unroll
        for (int i = 0; i < 4; ++i) {
            os[i] += __shfl_xor_sync(0xffffffffu, os[i], 1);
            os[i] += __shfl_xor_sync(0xffffffffu, os[i], 2);
        }
        float* outp = (float*)(smem + SM_OUTP);
        if ((lane & 3) == 0) {
            #pragma unroll
            for (int mt = 0; mt < 2; ++mt)
                #pragma unroll
                for (int rh = 0; rh < 2; ++rh) {
                    int r = m0w + mt * 16 + rh * 8 + eRow;
                    outp[warpG * TP + r] = os[mt * 2 + rh];
                }
        }
        __syncthreads();
        if (tid < TP) out[pt0 + tid] = outp[tid] + outp[TP + tid] + *bout;
    }
}

// ---------------------------------------------------------------------------
extern "C" void kernel_launch(void* const* d_in, const int* in_sizes, int n_in,
                              void* d_out, int out_size) {
    const float* x     = (const float*)d_in[0];
    const float* a     = (const float*)d_in[1];
    const float* Wftr  = (const float*)d_in[2];
    const float* bftr  = (const float*)d_in[3];
    const float* Wfwd  = (const float*)d_in[4];
    const float* bfwd  = (const float*)d_in[5];
    const float* Wcode = (const float*)d_in[6];
    const float* bcode = (const float*)d_in[7];
    const float* Wout  = (const float*)d_in[8];
    const float* bout  = (const float*)d_in[9];
    float* out = (float*)d_out;

    prep_all<<<NCODE_BLK + NW_BLK, 256>>>(a, Wcode, bcode, Wfwd, Wftr);

    cudaFuncSetAttribute(sinr_mma, cudaFuncAttributeMaxDynamicSharedMemorySize,
                         SM_TOTAL);
    sinr_mma<<<TOTAL_PTS / TP, 256, SM_TOTAL>>>(x, bftr, bfwd, Wout, bout, out);

    if (out_size >= TOTAL_PTS + in_sizes[0]) {
        cudaMemcpyAsync(out + TOTAL_PTS, x, (size_t)in_sizes[0] * sizeof(float),
                        cudaMemcpyDeviceToDevice);
    }
}

// round 8
// speedup vs baseline: 2.6871x; 1.1476x over previous
#include <cuda_runtime.h>
#include <cuda_bf16.h>
#include <math.h>
#include <stdint.h>

#ifndef M_PI
#define M_PI 3.14159265358979323846
#endif

#define DEPTH 5
#define HID 128
#define CODE_D 400
#define NFREQ 9
#define NB 8
#define NPTS 32768
#define TP 128
#define TOTAL_PTS (NB * NPTS)
#define NTHR 512

#define PZ 136   // bf16 pitch for 128-col tiles (Z, W)
#define PY 24    // bf16 pitch for 16-col tiles (Y, F)

// ---------------------------------------------------------------------------
// Device scratch (no cudaMalloc allowed)
// ---------------------------------------------------------------------------
__device__ float g_code[DEPTH][NB][HID];
__device__ float g_norm[5][6];
__device__ __align__(16) __nv_bfloat16 g_wt[DEPTH][2][HID * PZ];      // hi/lo
__device__ __align__(16) __nv_bfloat16 g_ft[DEPTH + 1][2][HID * PY];  // hi/lo

// ---------------------------------------------------------------------------
// SMEM byte map
// ---------------------------------------------------------------------------
#define SM_CB    0
#define SM_FB    512
#define SM_WOUT  1024
#define SM_OUTP  1536                 // float[2][128]
#define SM_YS    2560                 // 6*128*9 f32 = 27648
#define SM_ZH    30208                // 128*136*2 = 34816
#define SM_ZL    65024
#define SM_WH    99840
#define SM_WL    134656
#define SM_YH    169472               // 128*24*2 = 6144
#define SM_YL    175616
#define SM_FH    181760
#define SM_FL    187904
#define SM_TOTAL 194048

// ---------------------------------------------------------------------------
// PTX helpers
// ---------------------------------------------------------------------------
__device__ __forceinline__ uint32_t smem_u32(const void* p) {
    uint32_t a;
    asm("{ .reg .u64 t; cvta.to.shared.u64 t, %1; cvt.u32.u64 %0, t; }"
        : "=r"(a) : "l"(p));
    return a;
}
__device__ __forceinline__ void ldsm4(uint32_t* r, uint32_t addr) {
    asm volatile("ldmatrix.sync.aligned.m8n8.x4.shared.b16 {%0,%1,%2,%3}, [%4];"
                 : "=r"(r[0]), "=r"(r[1]), "=r"(r[2]), "=r"(r[3]) : "r"(addr));
}
__device__ __forceinline__ void ldsm2(uint32_t* r, uint32_t addr) {
    asm volatile("ldmatrix.sync.aligned.m8n8.x2.shared.b16 {%0,%1}, [%2];"
                 : "=r"(r[0]), "=r"(r[1]) : "r"(addr));
}
__device__ __forceinline__ void mma16816(float* d, const uint32_t* a, const uint32_t* b) {
    asm volatile(
        "mma.sync.aligned.m16n8k16.row.col.f32.bf16.bf16.f32 "
        "{%0,%1,%2,%3}, {%4,%5,%6,%7}, {%8,%9}, {%0,%1,%2,%3};"
        : "+f"(d[0]), "+f"(d[1]), "+f"(d[2]), "+f"(d[3])
        : "r"(a[0]), "r"(a[1]), "r"(a[2]), "r"(a[3]), "r"(b[0]), "r"(b[1]));
}
__device__ __forceinline__ void split2(float z0, float z1, uint32_t& hi, uint32_t& lo) {
    uint32_t h;
    asm("cvt.rn.bf16x2.f32 %0, %1, %2;" : "=r"(h) : "f"(z1), "f"(z0));
    float h0 = __uint_as_float(h << 16);
    float h1 = __uint_as_float(h & 0xffff0000u);
    asm("cvt.rn.bf16x2.f32 %0, %1, %2;" : "=r"(lo) : "f"(z1 - h1), "f"(z0 - h0));
    hi = h;
}
__device__ __forceinline__ void cpa16(uint32_t dst, const void* src) {
    asm volatile("cp.async.cg.shared.global [%0], [%1], 16;" :: "r"(dst), "l"(src));
}
#define CP_COMMIT() asm volatile("cp.async.commit_group;" ::: "memory")
#define CP_WAIT(n)  asm volatile("cp.async.wait_group %0;" :: "n"(n) : "memory")

// ---------------------------------------------------------------------------
// Merged prep kernel
// ---------------------------------------------------------------------------
#define NCODE_BLK (DEPTH * NB * HID / 8)       // 640 (8 warps/block)
#define WT_ELEMS (DEPTH * HID * PZ)            // 87040
#define FT_ELEMS ((DEPTH + 1) * HID * PY)      // 18432
#define NW_BLK ((WT_ELEMS + FT_ELEMS + 255) / 256)

__global__ void prep_all(const float* __restrict__ a,
                         const float* __restrict__ Wcode,
                         const float* __restrict__ bcode,
                         const float* __restrict__ Wfwd,
                         const float* __restrict__ Wftr) {
    int blk = blockIdx.x, tid = threadIdx.x;
    if (blk < NCODE_BLK) {
        int wid = tid >> 5, lane = tid & 31;
        int gw = blk * 8 + wid;
        int layer = gw >> 10;
        int rem = gw & 1023;
        int b = rem >> 7, h = rem & 127;
        const float* wc = Wcode + (size_t)(layer * HID + h) * CODE_D;
        const float* av = a + b * CODE_D;
        float s = 0.f;
        for (int c = lane; c < CODE_D; c += 32) s = fmaf(av[c], wc[c], s);
        #pragma unroll
        for (int o = 16; o > 0; o >>= 1) s += __shfl_xor_sync(0xffffffffu, s, o);
        if (lane == 0) g_code[layer][b][h] = s + bcode[layer * HID + h];
        if (blk == 0 && wid == 0 && lane < 30) {
            int am = lane / 6, sh = lane % 6, l = am + sh;
            double r = 1.0;
            for (int k = l - am + 1; k <= l + am; ++k) r /= (double)k;
            g_norm[am][sh] = (float)sqrt((2.0 * l + 1.0) / (4.0 * M_PI) * r);
        }
    } else {
        int i = (blk - NCODE_BLK) * 256 + tid;
        if (i < WT_ELEMS) {
            int l = i / (HID * PZ), r = i % (HID * PZ), g = r / PZ, c = r % PZ;
            float v = (c < HID) ? Wfwd[(l * HID + g) * HID + c] : 0.f;
            __nv_bfloat16 hi = __float2bfloat16(v);
            __nv_bfloat16 lo = __float2bfloat16(v - __bfloat162float(hi));
            g_wt[l][0][r] = hi;
            g_wt[l][1][r] = lo;
        } else if (i < WT_ELEMS + FT_ELEMS) {
            int j = i - WT_ELEMS;
            int s = j / (HID * PY), r = j % (HID * PY), h = r / PY, f = r % PY;
            float v = (f < NFREQ) ? Wftr[(s * HID + h) * NFREQ + f] : 0.f;
            __nv_bfloat16 hi = __float2bfloat16(v);
            __nv_bfloat16 lo = __float2bfloat16(v - __bfloat162float(hi));
            g_ft[s][0][r] = hi;
            g_ft[s][1][r] = lo;
        }
    }
}

// ---------------------------------------------------------------------------
// Main kernel: 1 block = 128 points, 512 threads (16 warps), warp tile 16x64
// ---------------------------------------------------------------------------
__global__ __launch_bounds__(NTHR, 1)
void sinr_mma(const float* __restrict__ x,
              const float* __restrict__ bftr,
              const float* __restrict__ bfwd,
              const float* __restrict__ Wout,
              const float* __restrict__ bout,
              float* __restrict__ out) {
    extern __shared__ char smem[];
    const uint32_t sb = smem_u32(smem);
    const int tid = threadIdx.x, wid = tid >> 5, lane = tid & 31;
    const int blk = blockIdx.x, pt0 = blk * TP, b = blk >> 8;

    const int warpP = wid & 7, warpG = wid >> 3;
    const int m0w = warpP * 16, n0w = warpG * 64;

    // ---- issue F[0] group, then W[0] group ----
    {
        const char* fs = (const char*)g_ft[0];
        for (int i = tid; i < 768; i += NTHR)
            cpa16(sb + SM_FH + i * 16, fs + i * 16);
        CP_COMMIT();
        const char* ws = (const char*)g_wt[0];
        for (int i = tid; i < 4352; i += NTHR)
            cpa16(sb + SM_WH + i * 16, ws + i * 16);
        CP_COMMIT();
    }

    // ---- spherical harmonics into Ys (fp32), one point per thread ----
    if (tid < TP) {
        float theta = x[(pt0 + tid) * 2 + 0];
        float phi   = x[(pt0 + tid) * 2 + 1];
        float c = cosf(phi);
        float s2 = sqrtf(fmaxf(1.f - c * c, 0.f));
        float P[5][6];
        float pmm = 1.f;
        #pragma unroll
        for (int am = 0; am < 5; ++am) {
            if (am > 0) pmm *= -(2.f * am - 1.f) * s2;
            float p0 = pmm;
            P[am][0] = p0;
            float p1 = c * (2.f * am + 1.f) * pmm;
            P[am][1] = p1;
            #pragma unroll
            for (int sh = 2; sh < 6; ++sh) {
                int l = am + sh;
                float pl = ((2.f * l - 1.f) * c * p1 - (l + am - 1.f) * p0) * (1.f / (float)sh);
                p0 = p1; p1 = pl;
                P[am][sh] = pl;
            }
        }
        float ck[5], sk[5], c1, s1;
        sincosf(theta, &s1, &c1);
        ck[0] = 1.f; sk[0] = 0.f;
        ck[1] = c1;  sk[1] = s1;
        #pragma unroll
        for (int m = 2; m < 5; ++m) {
            ck[m] = c1 * ck[m - 1] - s1 * sk[m - 1];
            sk[m] = s1 * ck[m - 1] + c1 * sk[m - 1];
        }
        const float SQ2 = 1.41421356237309515f;
        float* Ys = (float*)(smem + SM_YS);
        #pragma unroll
        for (int s = 0; s < 6; ++s) {
            float* yrow = &Ys[(s * TP + tid) * NFREQ];
            yrow[4] = g_norm[0][s] * P[0][s];
            #pragma unroll
            for (int am = 1; am < 5; ++am) {
                float base = SQ2 * g_norm[am][s] * P[am][s];
                if (am & 1) base = -base;
                yrow[4 + am] = base * ck[am];
                yrow[4 - am] = base * sk[am];
            }
        }
    }

    // ---- init staging: fb0, wout, outp zero; split Y0 (+zero pad) ----
    if (tid < TP) {
        ((float*)(smem + SM_FB))[tid] = bftr[tid];
        ((float*)(smem + SM_WOUT))[tid] = Wout[tid];
        ((float*)(smem + SM_OUTP))[tid] = 0.f;
        ((float*)(smem + SM_OUTP))[TP + tid] = 0.f;
        const float* yr = (const float*)(smem + SM_YS) + tid * NFREQ;
        __nv_bfloat16* yh = (__nv_bfloat16*)(smem + SM_YH) + tid * PY;
        __nv_bfloat16* yl = (__nv_bfloat16*)(smem + SM_YL) + tid * PY;
        #pragma unroll
        for (int f = 0; f < NFREQ; ++f) {
            float v = yr[f];
            __nv_bfloat16 h = __float2bfloat16(v);
            yh[f] = h;
            yl[f] = __float2bfloat16(v - __bfloat162float(h));
        }
        #pragma unroll
        for (int f = NFREQ; f < 16; ++f) { yh[f] = __float2bfloat16(0.f); yl[f] = __float2bfloat16(0.f); }
    }
    CP_WAIT(1);        // F[0] landed
    __syncthreads();

    // ldmatrix lane address components
    const uint32_t aRow = (uint32_t)(lane & 15);
    const uint32_t aK8  = (uint32_t)((lane >> 4) * 8);
    const uint32_t bRow = (uint32_t)((lane & 7) + ((lane >> 4) & 1) * 8);
    const uint32_t bK8  = (uint32_t)(((lane >> 3) & 1) * 8);
    const uint32_t fRow = (uint32_t)(lane & 7);
    const uint32_t fK8  = (uint32_t)(((lane >> 3) & 1) * 8);

    const float* cb  = (const float*)(smem + SM_CB);
    const float* fb  = (const float*)(smem + SM_FB);
    const float* wos = (const float*)(smem + SM_WOUT);

    const int eRow = lane >> 2;
    const int eCol = (lane & 3) * 2;

    // ---- init: z0 = Y0*Wftr0^T + bftr0 (feature mma only) ----
    {
        uint32_t Yh[4], Yl[4];
        uint32_t ro = ((uint32_t)m0w + aRow) * (PY * 2) + aK8 * 2;
        ldsm4(Yh, sb + SM_YH + ro);
        ldsm4(Yl, sb + SM_YL + ro);
        #pragma unroll
        for (int nt = 0; nt < 8; ++nt) {
            int n0 = n0w + nt * 8;
            uint32_t Fh[2], Fl[2];
            uint32_t fo = ((uint32_t)n0 + fRow) * (PY * 2) + fK8 * 2;
            ldsm2(Fh, sb + SM_FH + fo);
            ldsm2(Fl, sb + SM_FL + fo);
            float fa[4] = {0.f, 0.f, 0.f, 0.f};
            mma16816(fa, Yh, Fh);
            mma16816(fa, Yh, Fl);
            mma16816(fa, Yl, Fh);
            int c0 = n0 + eCol;
            float2 fbv = *(const float2*)&fb[c0];
            float z0 = fa[0] + fbv.x, z1 = fa[1] + fbv.y;
            float z2 = fa[2] + fbv.x, z3 = fa[3] + fbv.y;
            uint32_t hi, lo;
            int r0 = m0w + eRow;
            uint32_t o0 = (uint32_t)(r0 * (PZ * 2) + c0 * 2);
            uint32_t o1 = o0 + 8 * (PZ * 2);
            split2(z0, z1, hi, lo);
            *(uint32_t*)(smem + SM_ZH + o0) = hi;
            *(uint32_t*)(smem + SM_ZL + o0) = lo;
            split2(z2, z3, hi, lo);
            *(uint32_t*)(smem + SM_ZH + o1) = hi;
            *(uint32_t*)(smem + SM_ZL + o1) = lo;
        }
    }
    __syncthreads();   // protect Y/F buffers before loop-top restaging

    float os[2] = {0.f, 0.f};

    // =========================== 5 fused layers =============================
    for (int l = 0; l < DEPTH; ++l) {
        // ---- issue F[l+1] cp.async; stage biases + Y[l+1] split ----
        {
            const char* fs = (const char*)g_ft[l + 1];
            for (int i = tid; i < 768; i += NTHR)
                cpa16(sb + SM_FH + i * 16, fs + i * 16);
            CP_COMMIT();
            if (tid < TP) {
                ((float*)(smem + SM_FB))[tid] = bftr[(l + 1) * HID + tid];
                ((float*)(smem + SM_CB))[tid] = g_code[l][b][tid] + bfwd[l * HID + tid];
                const float* yr = (const float*)(smem + SM_YS) + ((l + 1) * TP + tid) * NFREQ;
                __nv_bfloat16* yh = (__nv_bfloat16*)(smem + SM_YH) + tid * PY;
                __nv_bfloat16* yl = (__nv_bfloat16*)(smem + SM_YL) + tid * PY;
                #pragma unroll
                for (int f = 0; f < NFREQ; ++f) {
                    float v = yr[f];
                    __nv_bfloat16 h = __float2bfloat16(v);
                    yh[f] = h;
                    yl[f] = __float2bfloat16(v - __bfloat162float(h));
                }
            }
        }
        CP_WAIT(1);        // W[l] landed
        __syncthreads();

        // ---- main GEMM: acc = Z * W^T (split 3-term), warp tile 16x64 ----
        float acc[8][4];
        #pragma unroll
        for (int nt = 0; nt < 8; ++nt)
            #pragma unroll
            for (int r = 0; r < 4; ++r) acc[nt][r] = 0.f;

        #pragma unroll
        for (int ks = 0; ks < 8; ++ks) {
            const uint32_t k0 = ks * 16;
            uint32_t Ah[4], Al[4];
            {
                uint32_t ro = ((uint32_t)m0w + aRow) * (PZ * 2) + (k0 + aK8) * 2;
                ldsm4(Ah, sb + SM_ZH + ro);
                ldsm4(Al, sb + SM_ZL + ro);
            }
            uint32_t Bh[8][2], Bl[8][2];
            #pragma unroll
            for (int np = 0; np < 4; ++np) {
                uint32_t ro = ((uint32_t)(n0w + np * 16) + bRow) * (PZ * 2) + (k0 + bK8) * 2;
                uint32_t t[4];
                ldsm4(t, sb + SM_WH + ro);
                Bh[np * 2][0] = t[0]; Bh[np * 2][1] = t[1];
                Bh[np * 2 + 1][0] = t[2]; Bh[np * 2 + 1][1] = t[3];
                ldsm4(t, sb + SM_WL + ro);
                Bl[np * 2][0] = t[0]; Bl[np * 2][1] = t[1];
                Bl[np * 2 + 1][0] = t[2]; Bl[np * 2 + 1][1] = t[3];
            }
            #pragma unroll
            for (int nt = 0; nt < 8; ++nt) {
                mma16816(acc[nt], Ah, Bh[nt]);
                mma16816(acc[nt], Ah, Bl[nt]);
                mma16816(acc[nt], Al, Bh[nt]);
            }
        }

        CP_WAIT(0);        // F[l+1] landed
        __syncthreads();   // all W reads done + F visible

        // ---- prefetch next layer's W while epilogue runs ----
        if (l + 1 < DEPTH) {
            const char* ws = (const char*)g_wt[l + 1];
            for (int i = tid; i < 4352; i += NTHR)
                cpa16(sb + SM_WH + i * 16, ws + i * 16);
        }
        CP_COMMIT();

        // ---- epilogue: feat mma + combine + writeback / output ----
        {
            uint32_t Yh[4], Yl[4];
            uint32_t ro = ((uint32_t)m0w + aRow) * (PY * 2) + aK8 * 2;
            ldsm4(Yh, sb + SM_YH + ro);
            ldsm4(Yl, sb + SM_YL + ro);
            #pragma unroll
            for (int nt = 0; nt < 8; ++nt) {
                int n0 = n0w + nt * 8;
                uint32_t Fh[2], Fl[2];
                uint32_t fo = ((uint32_t)n0 + fRow) * (PY * 2) + fK8 * 2;
                ldsm2(Fh, sb + SM_FH + fo);
                ldsm2(Fl, sb + SM_FL + fo);
                int c0 = n0 + eCol;
                float2 fbv = *(const float2*)&fb[c0];
                float2 cbv = *(const float2*)&cb[c0];
                float fa[4] = {0.f, 0.f, 0.f, 0.f};
                mma16816(fa, Yh, Fh);
                mma16816(fa, Yh, Fl);
                mma16816(fa, Yl, Fh);
                float z0 = (acc[nt][0] + cbv.x) * (fa[0] + fbv.x);
                float z1 = (acc[nt][1] + cbv.y) * (fa[1] + fbv.y);
                float z2 = (acc[nt][2] + cbv.x) * (fa[2] + fbv.x);
                float z3 = (acc[nt][3] + cbv.y) * (fa[3] + fbv.y);
                if (l < DEPTH - 1) {
                    uint32_t hi, lo;
                    int r0 = m0w + eRow;
                    uint32_t o0 = (uint32_t)(r0 * (PZ * 2) + c0 * 2);
                    uint32_t o1 = o0 + 8 * (PZ * 2);
                    split2(z0, z1, hi, lo);
                    *(uint32_t*)(smem + SM_ZH + o0) = hi;
                    *(uint32_t*)(smem + SM_ZL + o0) = lo;
                    split2(z2, z3, hi, lo);
                    *(uint32_t*)(smem + SM_ZH + o1) = hi;
                    *(uint32_t*)(smem + SM_ZL + o1) = lo;
                } else {
                    float2 wv = *(const float2*)&wos[c0];
                    os[0] = fmaf(z0, wv.x, fmaf(z1, wv.y, os[0]));
                    os[1] = fmaf(z2, wv.x, fmaf(z3, wv.y, os[1]));
                }
            }
        }
        __syncthreads();   // epilogue reads + Z writes done
    }

    // ---- output reduce ----
    {
        #pragma unroll
        for (int i = 0; i < 2; ++i) {
            os[i] += __shfl_xor_sync(0xffffffffu, os[i], 1);
            os[i] += __shfl_xor_sync(0xffffffffu, os[i], 2);
        }
        float* outp = (float*)(smem + SM_OUTP);
        if ((lane & 3) == 0) {
            outp[warpG * TP + m0w + eRow]     = os[0];
            outp[warpG * TP + m0w + 8 + eRow] = os[1];
        }
        __syncthreads();
        if (tid < TP) out[pt0 + tid] = outp[tid] + outp[TP + tid] + *bout;
    }
}

// ---------------------------------------------------------------------------
extern "C" void kernel_launch(void* const* d_in, const int* in_sizes, int n_in,
                              void* d_out, int out_size) {
    const float* x     = (const float*)d_in[0];
    const float* a     = (const float*)d_in[1];
    const float* Wftr  = (const float*)d_in[2];
    const float* bftr  = (const float*)d_in[3];
    const float* Wfwd  = (const float*)d_in[4];
    const float* bfwd  = (const float*)d_in[5];
    const float* Wcode = (const float*)d_in[6];
    const float* bcode = (const float*)d_in[7];
    const float* Wout  = (const float*)d_in[8];
    const float* bout  = (const float*)d_in[9];
    float* out = (float*)d_out;

    prep_all<<<NCODE_BLK + NW_BLK, 256>>>(a, Wcode, bcode, Wfwd, Wftr);

    cudaFuncSetAttribute(sinr_mma, cudaFuncAttributeMaxDynamicSharedMemorySize,
                         SM_TOTAL);
    sinr_mma<<<TOTAL_PTS / TP, NTHR, SM_TOTAL>>>(x, bftr, bfwd, Wout, bout, out);

    if (out_size >= TOTAL_PTS + in_sizes[0]) {
        cudaMemcpyAsync(out + TOTAL_PTS, x, (size_t)in_sizes[0] * sizeof(float),
                        cudaMemcpyDeviceToDevice);
    }
}

// round 9
// speedup vs baseline: 2.8588x; 1.0639x over previous
#include <cuda_runtime.h>
#include <cuda_bf16.h>
#include <math.h>
#include <stdint.h>

#ifndef M_PI
#define M_PI 3.14159265358979323846
#endif

#define DEPTH 5
#define HID 128
#define CODE_D 400
#define NFREQ 9
#define NB 8
#define NPTS 32768
#define TP 128
#define TOTAL_PTS (NB * NPTS)
#define NTHR 512

#define PZ 136   // bf16 pitch for 128-col tiles (Z, W)
#define PY 24    // bf16 pitch for 16-col tiles (Y, F)

// ---------------------------------------------------------------------------
// Device scratch
// ---------------------------------------------------------------------------
__device__ float g_code[DEPTH][NB][HID];
__device__ float g_norm[5][6];
__device__ __align__(16) __nv_bfloat16 g_wt[DEPTH][2][HID * PZ];      // hi/lo
__device__ __align__(16) __nv_bfloat16 g_ft[DEPTH + 1][2][HID * PY];  // hi/lo

// ---------------------------------------------------------------------------
// SMEM byte map (219,648 B total)
// ---------------------------------------------------------------------------
#define SM_CBB   0            // 2 x 128 f32 (code+bfwd bias, ping-pong)
#define SM_FBB   1024         // 2 x 128 f32 (bftr bias, ping-pong)
#define SM_WOUT  2048
#define SM_OUTP  2560         // float[2][128]
#define SM_YS    3584         // 6*128*9 f32 = 27648
#define SM_ZH    31232        // 128*136*2 = 34816
#define SM_ZL    66048
#define SM_WH    100864
#define SM_WL    135680
#define SM_YB    170496       // 2 bufs x (H 6144 | L 6144) = 24576
#define SM_FT    195072       // 2 bufs x (H 6144 | L 6144) = 24576
#define SM_TOTAL 219648

#define YBSTRIDE 12288
#define HALFOFF  6144

// ---------------------------------------------------------------------------
// PTX helpers
// ---------------------------------------------------------------------------
__device__ __forceinline__ uint32_t smem_u32(const void* p) {
    uint32_t a;
    asm("{ .reg .u64 t; cvta.to.shared.u64 t, %1; cvt.u32.u64 %0, t; }"
        : "=r"(a) : "l"(p));
    return a;
}
__device__ __forceinline__ void ldsm4(uint32_t* r, uint32_t addr) {
    asm volatile("ldmatrix.sync.aligned.m8n8.x4.shared.b16 {%0,%1,%2,%3}, [%4];"
                 : "=r"(r[0]), "=r"(r[1]), "=r"(r[2]), "=r"(r[3]) : "r"(addr));
}
__device__ __forceinline__ void ldsm2(uint32_t* r, uint32_t addr) {
    asm volatile("ldmatrix.sync.aligned.m8n8.x2.shared.b16 {%0,%1}, [%2];"
                 : "=r"(r[0]), "=r"(r[1]) : "r"(addr));
}
__device__ __forceinline__ void mma16816(float* d, const uint32_t* a, const uint32_t* b) {
    asm volatile(
        "mma.sync.aligned.m16n8k16.row.col.f32.bf16.bf16.f32 "
        "{%0,%1,%2,%3}, {%4,%5,%6,%7}, {%8,%9}, {%0,%1,%2,%3};"
        : "+f"(d[0]), "+f"(d[1]), "+f"(d[2]), "+f"(d[3])
        : "r"(a[0]), "r"(a[1]), "r"(a[2]), "r"(a[3]), "r"(b[0]), "r"(b[1]));
}
__device__ __forceinline__ void split2(float z0, float z1, uint32_t& hi, uint32_t& lo) {
    uint32_t h;
    asm("cvt.rn.bf16x2.f32 %0, %1, %2;" : "=r"(h) : "f"(z1), "f"(z0));
    float h0 = __uint_as_float(h << 16);
    float h1 = __uint_as_float(h & 0xffff0000u);
    asm("cvt.rn.bf16x2.f32 %0, %1, %2;" : "=r"(lo) : "f"(z1 - h1), "f"(z0 - h0));
    hi = h;
}
__device__ __forceinline__ void cpa16(uint32_t dst, const void* src) {
    asm volatile("cp.async.cg.shared.global [%0], [%1], 16;" :: "r"(dst), "l"(src));
}
#define CP_COMMIT() asm volatile("cp.async.commit_group;" ::: "memory")
#define CP_WAIT(n)  asm volatile("cp.async.wait_group %0;" :: "n"(n) : "memory")

// ---------------------------------------------------------------------------
// Merged prep kernel
// ---------------------------------------------------------------------------
#define NCODE_BLK (DEPTH * NB * HID / 8)
#define WT_ELEMS (DEPTH * HID * PZ)
#define FT_ELEMS ((DEPTH + 1) * HID * PY)
#define NW_BLK ((WT_ELEMS + FT_ELEMS + 255) / 256)

__global__ void prep_all(const float* __restrict__ a,
                         const float* __restrict__ Wcode,
                         const float* __restrict__ bcode,
                         const float* __restrict__ Wfwd,
                         const float* __restrict__ Wftr) {
    int blk = blockIdx.x, tid = threadIdx.x;
    if (blk < NCODE_BLK) {
        int wid = tid >> 5, lane = tid & 31;
        int gw = blk * 8 + wid;
        int layer = gw >> 10;
        int rem = gw & 1023;
        int b = rem >> 7, h = rem & 127;
        const float* wc = Wcode + (size_t)(layer * HID + h) * CODE_D;
        const float* av = a + b * CODE_D;
        float s = 0.f;
        for (int c = lane; c < CODE_D; c += 32) s = fmaf(av[c], wc[c], s);
        #pragma unroll
        for (int o = 16; o > 0; o >>= 1) s += __shfl_xor_sync(0xffffffffu, s, o);
        if (lane == 0) g_code[layer][b][h] = s + bcode[layer * HID + h];
        if (blk == 0 && wid == 0 && lane < 30) {
            int am = lane / 6, sh = lane % 6, l = am + sh;
            double r = 1.0;
            for (int k = l - am + 1; k <= l + am; ++k) r /= (double)k;
            g_norm[am][sh] = (float)sqrt((2.0 * l + 1.0) / (4.0 * M_PI) * r);
        }
    } else {
        int i = (blk - NCODE_BLK) * 256 + tid;
        if (i < WT_ELEMS) {
            int l = i / (HID * PZ), r = i % (HID * PZ), g = r / PZ, c = r % PZ;
            float v = (c < HID) ? Wfwd[(l * HID + g) * HID + c] : 0.f;
            __nv_bfloat16 hi = __float2bfloat16(v);
            __nv_bfloat16 lo = __float2bfloat16(v - __bfloat162float(hi));
            g_wt[l][0][r] = hi;
            g_wt[l][1][r] = lo;
        } else if (i < WT_ELEMS + FT_ELEMS) {
            int j = i - WT_ELEMS;
            int s = j / (HID * PY), r = j % (HID * PY), h = r / PY, f = r % PY;
            float v = (f < NFREQ) ? Wftr[(s * HID + h) * NFREQ + f] : 0.f;
            __nv_bfloat16 hi = __float2bfloat16(v);
            __nv_bfloat16 lo = __float2bfloat16(v - __bfloat162float(hi));
            g_ft[s][0][r] = hi;
            g_ft[s][1][r] = lo;
        }
    }
}

// ---------------------------------------------------------------------------
// Main kernel
// ---------------------------------------------------------------------------
__global__ __launch_bounds__(NTHR, 1)
void sinr_mma(const float* __restrict__ x,
              const float* __restrict__ bftr,
              const float* __restrict__ bfwd,
              const float* __restrict__ Wout,
              const float* __restrict__ bout,
              float* __restrict__ out) {
    extern __shared__ char smem[];
    const uint32_t sb = smem_u32(smem);
    const int tid = threadIdx.x, wid = tid >> 5, lane = tid & 31;
    const int blk = blockIdx.x, pt0 = blk * TP, b = blk >> 8;

    const int warpP = wid & 7, warpG = wid >> 3;
    const int m0w = warpP * 16, n0w = warpG * 64;

    // ---- prologue cp.async: F0 (g1), W0 (g2), F1 (g3) ----
    {
        const char* f0 = (const char*)g_ft[0];
        for (int i = tid; i < 768; i += NTHR)
            cpa16(sb + SM_FT + i * 16, f0 + i * 16);
        CP_COMMIT();
        const char* ws = (const char*)g_wt[0];
        for (int i = tid; i < 4352; i += NTHR)
            cpa16(sb + SM_WH + i * 16, ws + i * 16);
        CP_COMMIT();
        const char* f1 = (const char*)g_ft[1];
        for (int i = tid; i < 768; i += NTHR)
            cpa16(sb + SM_FT + YBSTRIDE + i * 16, f1 + i * 16);
        CP_COMMIT();
    }

    // ---- spherical harmonics into Ys (fp32), one point per thread ----
    if (tid < TP) {
        float theta = x[(pt0 + tid) * 2 + 0];
        float phi   = x[(pt0 + tid) * 2 + 1];
        float c = cosf(phi);
        float s2 = sqrtf(fmaxf(1.f - c * c, 0.f));
        float P[5][6];
        float pmm = 1.f;
        #pragma unroll
        for (int am = 0; am < 5; ++am) {
            if (am > 0) pmm *= -(2.f * am - 1.f) * s2;
            float p0 = pmm;
            P[am][0] = p0;
            float p1 = c * (2.f * am + 1.f) * pmm;
            P[am][1] = p1;
            #pragma unroll
            for (int sh = 2; sh < 6; ++sh) {
                int l = am + sh;
                float pl = ((2.f * l - 1.f) * c * p1 - (l + am - 1.f) * p0) * (1.f / (float)sh);
                p0 = p1; p1 = pl;
                P[am][sh] = pl;
            }
        }
        float ck[5], sk[5], c1, s1;
        sincosf(theta, &s1, &c1);
        ck[0] = 1.f; sk[0] = 0.f;
        ck[1] = c1;  sk[1] = s1;
        #pragma unroll
        for (int m = 2; m < 5; ++m) {
            ck[m] = c1 * ck[m - 1] - s1 * sk[m - 1];
            sk[m] = s1 * ck[m - 1] + c1 * sk[m - 1];
        }
        const float SQ2 = 1.41421356237309515f;
        float* Ys = (float*)(smem + SM_YS);
        #pragma unroll
        for (int s = 0; s < 6; ++s) {
            float* yrow = &Ys[(s * TP + tid) * NFREQ];
            yrow[4] = g_norm[0][s] * P[0][s];
            #pragma unroll
            for (int am = 1; am < 5; ++am) {
                float base = SQ2 * g_norm[am][s] * P[am][s];
                if (am & 1) base = -base;
                yrow[4 + am] = base * ck[am];
                yrow[4 - am] = base * sk[am];
            }
        }
    }

    // ---- Y split helper macro: shift s -> YB buffer (tid-local YS reads) ----
    #define SPLIT_Y(s, buf)                                                      \
        {                                                                        \
            const float* yr = (const float*)(smem + SM_YS) + ((s) * TP + tid) * NFREQ; \
            __nv_bfloat16* yh = (__nv_bfloat16*)(smem + SM_YB + (buf) * YBSTRIDE) + tid * PY; \
            __nv_bfloat16* yl = (__nv_bfloat16*)(smem + SM_YB + (buf) * YBSTRIDE + HALFOFF) + tid * PY; \
            _Pragma("unroll")                                                    \
            for (int f = 0; f < NFREQ; ++f) {                                    \
                float v = yr[f];                                                 \
                __nv_bfloat16 h = __float2bfloat16(v);                           \
                yh[f] = h;                                                       \
                yl[f] = __float2bfloat16(v - __bfloat162float(h));               \
            }                                                                    \
        }

    // ---- init staging: biases, wout, zero pad of both Y bufs, Y0/Y1 splits --
    if (tid < TP) {
        ((float*)(smem + SM_FBB))[tid] = bftr[tid];                 // fbb0 = fb[0]
        ((float*)(smem + SM_FBB))[TP + tid] = bftr[HID + tid];      // fbb1 = fb[1]
        ((float*)(smem + SM_CBB))[tid] = g_code[0][b][tid] + bfwd[tid]; // cbb0 = cb[0]
        ((float*)(smem + SM_WOUT))[tid] = Wout[tid];
        ((float*)(smem + SM_OUTP))[tid] = 0.f;
        ((float*)(smem + SM_OUTP))[TP + tid] = 0.f;
        // zero pad cols 9..15 of both Y buffers (hi+lo)
        #pragma unroll
        for (int bu = 0; bu < 2; ++bu) {
            __nv_bfloat16* yh = (__nv_bfloat16*)(smem + SM_YB + bu * YBSTRIDE) + tid * PY;
            __nv_bfloat16* yl = (__nv_bfloat16*)(smem + SM_YB + bu * YBSTRIDE + HALFOFF) + tid * PY;
            #pragma unroll
            for (int f = NFREQ; f < 16; ++f) { yh[f] = __float2bfloat16(0.f); yl[f] = __float2bfloat16(0.f); }
        }
        SPLIT_Y(0, 0);
        SPLIT_Y(1, 1);
    }
    CP_WAIT(2);      // F0 landed
    __syncthreads();

    // ldmatrix lane address components
    const uint32_t aRow = (uint32_t)(lane & 15);
    const uint32_t aK8  = (uint32_t)((lane >> 4) * 8);
    const uint32_t bRow = (uint32_t)((lane & 7) + ((lane >> 4) & 1) * 8);
    const uint32_t bK8  = (uint32_t)(((lane >> 3) & 1) * 8);
    const uint32_t fRow = (uint32_t)(lane & 7);
    const uint32_t fK8  = (uint32_t)(((lane >> 3) & 1) * 8);

    const float* wos = (const float*)(smem + SM_WOUT);
    const int eRow = lane >> 2;
    const int eCol = (lane & 3) * 2;

    const uint32_t roY = ((uint32_t)m0w + aRow) * (PY * 2) + aK8 * 2;
    const uint32_t foY = ((uint32_t)fRow) * (PY * 2) + fK8 * 2;

    // ---- init: z0 = Y0*Wftr0^T + fb0, split -> Z ----
    {
        uint32_t Yh[4], Yl[4];
        ldsm4(Yh, sb + SM_YB + roY);
        ldsm4(Yl, sb + SM_YB + HALFOFF + roY);
        const float* fb = (const float*)(smem + SM_FBB);
        #pragma unroll
        for (int nt = 0; nt < 8; ++nt) {
            int n0 = n0w + nt * 8;
            uint32_t Fh[2], Fl[2];
            uint32_t fo = (uint32_t)n0 * (PY * 2) + foY;
            ldsm2(Fh, sb + SM_FT + fo);
            ldsm2(Fl, sb + SM_FT + HALFOFF + fo);
            float fa[4] = {0.f, 0.f, 0.f, 0.f};
            mma16816(fa, Yh, Fh);
            mma16816(fa, Yh, Fl);
            mma16816(fa, Yl, Fh);
            int c0 = n0 + eCol;
            float2 fbv = *(const float2*)&fb[c0];
            uint32_t hi, lo;
            int r0 = m0w + eRow;
            uint32_t o0 = (uint32_t)(r0 * (PZ * 2) + c0 * 2);
            uint32_t o1 = o0 + 8 * (PZ * 2);
            split2(fa[0] + fbv.x, fa[1] + fbv.y, hi, lo);
            *(uint32_t*)(smem + SM_ZH + o0) = hi;
            *(uint32_t*)(smem + SM_ZL + o0) = lo;
            split2(fa[2] + fbv.x, fa[3] + fbv.y, hi, lo);
            *(uint32_t*)(smem + SM_ZH + o1) = hi;
            *(uint32_t*)(smem + SM_ZL + o1) = lo;
        }
    }
    CP_WAIT(0);      // W0 + F1 landed
    __syncthreads();

    float os[2] = {0.f, 0.f};

    // =========================== 5 fused layers =============================
    #pragma unroll 1
    for (int l = 0; l < DEPTH; ++l) {
        const int ping = l & 1;          // staging target
        const int pong = (l + 1) & 1;    // this layer's Y/F/fb source

        // ---- A: stage layer l+2 assets into ping buffers (no barrier) ----
        if (l <= 3) {
            const char* fs = (const char*)g_ft[l + 2];
            for (int i = tid; i < 768; i += NTHR)
                cpa16(sb + SM_FT + ping * YBSTRIDE + i * 16, fs + i * 16);
        }
        CP_COMMIT();
        if (tid < TP && l <= 3) {
            ((float*)(smem + SM_FBB))[ping * TP + tid] = bftr[(l + 2) * HID + tid];
            ((float*)(smem + SM_CBB))[pong * TP + tid] =
                g_code[l + 1][b][tid] + bfwd[(l + 1) * HID + tid];
            SPLIT_Y(l + 2, ping);
        }

        // ---- B: tensor burst: feature MMA (fa) then main GEMM (acc) ----
        float fa[8][4];
        {
            uint32_t Yh[4], Yl[4];
            uint32_t yb = sb + SM_YB + pong * YBSTRIDE;
            ldsm4(Yh, yb + roY);
            ldsm4(Yl, yb + HALFOFF + roY);
            uint32_t ft = sb + SM_FT + pong * YBSTRIDE;
            #pragma unroll
            for (int nt = 0; nt < 8; ++nt) {
                uint32_t fo = (uint32_t)(n0w + nt * 8) * (PY * 2) + foY;
                uint32_t Fh[2], Fl[2];
                ldsm2(Fh, ft + fo);
                ldsm2(Fl, ft + HALFOFF + fo);
                fa[nt][0] = fa[nt][1] = fa[nt][2] = fa[nt][3] = 0.f;
                mma16816(fa[nt], Yh, Fh);
                mma16816(fa[nt], Yh, Fl);
                mma16816(fa[nt], Yl, Fh);
            }
        }
        float acc[8][4];
        #pragma unroll
        for (int nt = 0; nt < 8; ++nt)
            #pragma unroll
            for (int r = 0; r < 4; ++r) acc[nt][r] = 0.f;
        #pragma unroll
        for (int ks = 0; ks < 8; ++ks) {
            const uint32_t k0 = ks * 16;
            uint32_t Ah[4], Al[4];
            {
                uint32_t ro = ((uint32_t)m0w + aRow) * (PZ * 2) + (k0 + aK8) * 2;
                ldsm4(Ah, sb + SM_ZH + ro);
                ldsm4(Al, sb + SM_ZL + ro);
            }
            #pragma unroll
            for (int np = 0; np < 4; ++np) {
                uint32_t ro = ((uint32_t)(n0w + np * 16) + bRow) * (PZ * 2) + (k0 + bK8) * 2;
                uint32_t t[4];
                ldsm4(t, sb + SM_WH + ro);
                mma16816(acc[np * 2],     Ah, t);
                mma16816(acc[np * 2 + 1], Ah, t + 2);
                mma16816(acc[np * 2],     Al, t);
                mma16816(acc[np * 2 + 1], Al, t + 2);
                ldsm4(t, sb + SM_WL + ro);
                mma16816(acc[np * 2],     Ah, t);
                mma16816(acc[np * 2 + 1], Ah, t + 2);
            }
        }

        // ---- C: all Z/W reads done ----
        __syncthreads();

        // ---- D: prefetch W[l+1] ----
        if (l + 1 < DEPTH) {
            const char* ws = (const char*)g_wt[l + 1];
            for (int i = tid; i < 4352; i += NTHR)
                cpa16(sb + SM_WH + i * 16, ws + i * 16);
        }
        CP_COMMIT();

        // ---- E: combine epilogue (pure fp32 + split + STS) ----
        {
            const float* cbp = (const float*)(smem + SM_CBB) + ping * TP;  // cb[l]: buf l&1
            const float* fbp = (const float*)(smem + SM_FBB) + pong * TP;  // fb[l+1]
            #pragma unroll
            for (int nt = 0; nt < 8; ++nt) {
                int c0 = n0w + nt * 8 + eCol;
                float2 fbv = *(const float2*)&fbp[c0];
                float2 cbv = *(const float2*)&cbp[c0];
                float z0 = (acc[nt][0] + cbv.x) * (fa[nt][0] + fbv.x);
                float z1 = (acc[nt][1] + cbv.y) * (fa[nt][1] + fbv.y);
                float z2 = (acc[nt][2] + cbv.x) * (fa[nt][2] + fbv.x);
                float z3 = (acc[nt][3] + cbv.y) * (fa[nt][3] + fbv.y);
                if (l < DEPTH - 1) {
                    uint32_t hi, lo;
                    int r0 = m0w + eRow;
                    uint32_t o0 = (uint32_t)(r0 * (PZ * 2) + c0 * 2);
                    uint32_t o1 = o0 + 8 * (PZ * 2);
                    split2(z0, z1, hi, lo);
                    *(uint32_t*)(smem + SM_ZH + o0) = hi;
                    *(uint32_t*)(smem + SM_ZL + o0) = lo;
                    split2(z2, z3, hi, lo);
                    *(uint32_t*)(smem + SM_ZH + o1) = hi;
                    *(uint32_t*)(smem + SM_ZL + o1) = lo;
                } else {
                    float2 wv = *(const float2*)&wos[c0];
                    os[0] = fmaf(z0, wv.x, fmaf(z1, wv.y, os[0]));
                    os[1] = fmaf(z2, wv.x, fmaf(z3, wv.y, os[1]));
                }
            }
        }

        // ---- G: wait all pending cp (F[l+2], W[l+1]) + barrier ----
        CP_WAIT(0);
        __syncthreads();
    }

    // ---- output reduce ----
    {
        #pragma unroll
        for (int i = 0; i < 2; ++i) {
            os[i] += __shfl_xor_sync(0xffffffffu, os[i], 1);
            os[i] += __shfl_xor_sync(0xffffffffu, os[i], 2);
        }
        float* outp = (float*)(smem + SM_OUTP);
        if ((lane & 3) == 0) {
            outp[warpG * TP + m0w + eRow]     = os[0];
            outp[warpG * TP + m0w + 8 + eRow] = os[1];
        }
        __syncthreads();
        if (tid < TP) out[pt0 + tid] = outp[tid] + outp[TP + tid] + *bout;
    }
}

// ---------------------------------------------------------------------------
extern "C" void kernel_launch(void* const* d_in, const int* in_sizes, int n_in,
                              void* d_out, int out_size) {
    const float* x     = (const float*)d_in[0];
    const float* a     = (const float*)d_in[1];
    const float* Wftr  = (const float*)d_in[2];
    const float* bftr  = (const float*)d_in[3];
    const float* Wfwd  = (const float*)d_in[4];
    const float* bfwd  = (const float*)d_in[5];
    const float* Wcode = (const float*)d_in[6];
    const float* bcode = (const float*)d_in[7];
    const float* Wout  = (const float*)d_in[8];
    const float* bout  = (const float*)d_in[9];
    float* out = (float*)d_out;

    prep_all<<<NCODE_BLK + NW_BLK, 256>>>(a, Wcode, bcode, Wfwd, Wftr);

    cudaFuncSetAttribute(sinr_mma, cudaFuncAttributeMaxDynamicSharedMemorySize,
                         SM_TOTAL);
    sinr_mma<<<TOTAL_PTS / TP, NTHR, SM_TOTAL>>>(x, bftr, bfwd, Wout, bout, out);

    if (out_size >= TOTAL_PTS + in_sizes[0]) {
        cudaMemcpyAsync(out + TOTAL_PTS, x, (size_t)in_sizes[0] * sizeof(float),
                        cudaMemcpyDeviceToDevice);
    }
}

// round 10
// speedup vs baseline: 2.9955x; 1.0478x over previous
#include <cuda_runtime.h>
#include <cuda_bf16.h>
#include <math.h>
#include <stdint.h>

#ifndef M_PI
#define M_PI 3.14159265358979323846
#endif

#define DEPTH 5
#define HID 128
#define CODE_D 400
#define NFREQ 9
#define NB 8
#define NPTS 32768
#define TP 128
#define TOTAL_PTS (NB * NPTS)
#define NTHR 512

#define PZ 136   // bf16 pitch for 128-col tiles (Z, W)  -> 272 B/row
#define PY 24    // bf16 pitch for 16-col tiles (Y, F)   -> 48 B/row

// ---------------------------------------------------------------------------
// Device scratch
// ---------------------------------------------------------------------------
__device__ float g_code[DEPTH][NB][HID];
__device__ float g_norm[5][6];
__device__ __align__(16) __nv_bfloat16 g_wt[DEPTH][2][HID * PZ];      // hi/lo
__device__ __align__(16) __nv_bfloat16 g_ft[DEPTH + 1][2][HID * PY];  // hi/lo

// ---------------------------------------------------------------------------
// SMEM byte map (220,672 B)
// ---------------------------------------------------------------------------
#define SM_CBB   0            // 2 x 128 f32 ping-pong (code+bfwd)
#define SM_FBB   1024         // 2 x 128 f32 ping-pong (bftr)
#define SM_WOUT  2048
#define SM_OUTP  2560         // float[4][128]
#define SM_YS    4608         // 6*128*9 f32 = 27648
#define SM_ZH    32256        // 128*272 = 34816
#define SM_ZL    67072
#define SM_WH    101888
#define SM_WL    136704
#define SM_YB    171520       // 2 bufs x (H|L) = 24576
#define SM_FT    196096       // 2 bufs x (H|L) = 24576
#define SM_TOTAL 220672

#define YBSTRIDE 12288
#define HALFOFF  6144

// ---------------------------------------------------------------------------
// PTX helpers
// ---------------------------------------------------------------------------
__device__ __forceinline__ uint32_t smem_u32(const void* p) {
    uint32_t a;
    asm("{ .reg .u64 t; cvta.to.shared.u64 t, %1; cvt.u32.u64 %0, t; }"
        : "=r"(a) : "l"(p));
    return a;
}
__device__ __forceinline__ void ldsm4(uint32_t* r, uint32_t addr) {
    asm volatile("ldmatrix.sync.aligned.m8n8.x4.shared.b16 {%0,%1,%2,%3}, [%4];"
                 : "=r"(r[0]), "=r"(r[1]), "=r"(r[2]), "=r"(r[3]) : "r"(addr));
}
__device__ __forceinline__ void ldsm2(uint32_t* r, uint32_t addr) {
    asm volatile("ldmatrix.sync.aligned.m8n8.x2.shared.b16 {%0,%1}, [%2];"
                 : "=r"(r[0]), "=r"(r[1]) : "r"(addr));
}
__device__ __forceinline__ void mma16816(float* d, const uint32_t* a, const uint32_t* b) {
    asm volatile(
        "mma.sync.aligned.m16n8k16.row.col.f32.bf16.bf16.f32 "
        "{%0,%1,%2,%3}, {%4,%5,%6,%7}, {%8,%9}, {%0,%1,%2,%3};"
        : "+f"(d[0]), "+f"(d[1]), "+f"(d[2]), "+f"(d[3])
        : "r"(a[0]), "r"(a[1]), "r"(a[2]), "r"(a[3]), "r"(b[0]), "r"(b[1]));
}
__device__ __forceinline__ void split2(float z0, float z1, uint32_t& hi, uint32_t& lo) {
    uint32_t h;
    asm("cvt.rn.bf16x2.f32 %0, %1, %2;" : "=r"(h) : "f"(z1), "f"(z0));
    float h0 = __uint_as_float(h << 16);
    float h1 = __uint_as_float(h & 0xffff0000u);
    asm("cvt.rn.bf16x2.f32 %0, %1, %2;" : "=r"(lo) : "f"(z1 - h1), "f"(z0 - h0));
    hi = h;
}
__device__ __forceinline__ void cpa16(uint32_t dst, const void* src) {
    asm volatile("cp.async.cg.shared.global [%0], [%1], 16;" :: "r"(dst), "l"(src));
}
#define CP_COMMIT() asm volatile("cp.async.commit_group;" ::: "memory")
#define CP_WAIT(n)  asm volatile("cp.async.wait_group %0;" :: "n"(n) : "memory")

// ---------------------------------------------------------------------------
// Merged prep kernel
// ---------------------------------------------------------------------------
#define NCODE_BLK (DEPTH * NB * HID / 8)
#define WT_ELEMS (DEPTH * HID * PZ)
#define FT_ELEMS ((DEPTH + 1) * HID * PY)
#define NW_BLK ((WT_ELEMS + FT_ELEMS + 255) / 256)

__global__ void prep_all(const float* __restrict__ a,
                         const float* __restrict__ Wcode,
                         const float* __restrict__ bcode,
                         const float* __restrict__ Wfwd,
                         const float* __restrict__ Wftr) {
    int blk = blockIdx.x, tid = threadIdx.x;
    if (blk < NCODE_BLK) {
        int wid = tid >> 5, lane = tid & 31;
        int gw = blk * 8 + wid;
        int layer = gw >> 10;
        int rem = gw & 1023;
        int b = rem >> 7, h = rem & 127;
        const float* wc = Wcode + (size_t)(layer * HID + h) * CODE_D;
        const float* av = a + b * CODE_D;
        float s = 0.f;
        for (int c = lane; c < CODE_D; c += 32) s = fmaf(av[c], wc[c], s);
        #pragma unroll
        for (int o = 16; o > 0; o >>= 1) s += __shfl_xor_sync(0xffffffffu, s, o);
        if (lane == 0) g_code[layer][b][h] = s + bcode[layer * HID + h];
        if (blk == 0 && wid == 0 && lane < 30) {
            int am = lane / 6, sh = lane % 6, l = am + sh;
            double r = 1.0;
            for (int k = l - am + 1; k <= l + am; ++k) r /= (double)k;
            g_norm[am][sh] = (float)sqrt((2.0 * l + 1.0) / (4.0 * M_PI) * r);
        }
    } else {
        int i = (blk - NCODE_BLK) * 256 + tid;
        if (i < WT_ELEMS) {
            int l = i / (HID * PZ), r = i % (HID * PZ), g = r / PZ, c = r % PZ;
            float v = (c < HID) ? Wfwd[(l * HID + g) * HID + c] : 0.f;
            __nv_bfloat16 hi = __float2bfloat16(v);
            __nv_bfloat16 lo = __float2bfloat16(v - __bfloat162float(hi));
            g_wt[l][0][r] = hi;
            g_wt[l][1][r] = lo;
        } else if (i < WT_ELEMS + FT_ELEMS) {
            int j = i - WT_ELEMS;
            int s = j / (HID * PY), r = j % (HID * PY), h = r / PY, f = r % PY;
            float v = (f < NFREQ) ? Wftr[(s * HID + h) * NFREQ + f] : 0.f;
            __nv_bfloat16 hi = __float2bfloat16(v);
            __nv_bfloat16 lo = __float2bfloat16(v - __bfloat162float(hi));
            g_ft[s][0][r] = hi;
            g_ft[s][1][r] = lo;
        }
    }
}

// ---------------------------------------------------------------------------
// Main kernel: 512 threads, 4x4 warp grid (warp tile 32m x 32n)
// ---------------------------------------------------------------------------
__global__ __launch_bounds__(NTHR, 1)
void sinr_mma(const float* __restrict__ x,
              const float* __restrict__ bftr,
              const float* __restrict__ bfwd,
              const float* __restrict__ Wout,
              const float* __restrict__ bout,
              float* __restrict__ out) {
    extern __shared__ char smem[];
    const uint32_t sb = smem_u32(smem);
    const int tid = threadIdx.x, wid = tid >> 5, lane = tid & 31;
    const int blk = blockIdx.x, pt0 = blk * TP, b = blk >> 8;

    const int warpP = wid & 3, warpG = wid >> 2;
    const int m0w = warpP * 32, n0w = warpG * 32;

    // ---- prologue cp.async: F0->buf0 (g1), W0 (g2), F1->buf1 (g3) ----
    {
        const char* f0 = (const char*)g_ft[0];
        for (int i = tid; i < 768; i += NTHR)
            cpa16(sb + SM_FT + i * 16, f0 + i * 16);
        CP_COMMIT();
        const char* ws = (const char*)g_wt[0];
        for (int i = tid; i < 4352; i += NTHR)
            cpa16(sb + SM_WH + i * 16, ws + i * 16);
        CP_COMMIT();
        const char* f1 = (const char*)g_ft[1];
        for (int i = tid; i < 768; i += NTHR)
            cpa16(sb + SM_FT + YBSTRIDE + i * 16, f1 + i * 16);
        CP_COMMIT();
    }

    // ---- spherical harmonics into Ys (fp32), one point per thread ----
    if (tid < TP) {
        float theta = x[(pt0 + tid) * 2 + 0];
        float phi   = x[(pt0 + tid) * 2 + 1];
        float c = cosf(phi);
        float s2 = sqrtf(fmaxf(1.f - c * c, 0.f));
        float P[5][6];
        float pmm = 1.f;
        #pragma unroll
        for (int am = 0; am < 5; ++am) {
            if (am > 0) pmm *= -(2.f * am - 1.f) * s2;
            float p0 = pmm;
            P[am][0] = p0;
            float p1 = c * (2.f * am + 1.f) * pmm;
            P[am][1] = p1;
            #pragma unroll
            for (int sh = 2; sh < 6; ++sh) {
                int l = am + sh;
                float pl = ((2.f * l - 1.f) * c * p1 - (l + am - 1.f) * p0) * (1.f / (float)sh);
                p0 = p1; p1 = pl;
                P[am][sh] = pl;
            }
        }
        float ck[5], sk[5], c1, s1;
        sincosf(theta, &s1, &c1);
        ck[0] = 1.f; sk[0] = 0.f;
        ck[1] = c1;  sk[1] = s1;
        #pragma unroll
        for (int m = 2; m < 5; ++m) {
            ck[m] = c1 * ck[m - 1] - s1 * sk[m - 1];
            sk[m] = s1 * ck[m - 1] + c1 * sk[m - 1];
        }
        const float SQ2 = 1.41421356237309515f;
        float* Ys = (float*)(smem + SM_YS);
        #pragma unroll
        for (int s = 0; s < 6; ++s) {
            float* yrow = &Ys[(s * TP + tid) * NFREQ];
            yrow[4] = g_norm[0][s] * P[0][s];
            #pragma unroll
            for (int am = 1; am < 5; ++am) {
                float base = SQ2 * g_norm[am][s] * P[am][s];
                if (am & 1) base = -base;
                yrow[4 + am] = base * ck[am];
                yrow[4 - am] = base * sk[am];
            }
        }
    }

    // ---- Y split macro: shift s -> YB buffer buf ----
    #define SPLIT_Y(s, buf)                                                      \
        {                                                                        \
            const float* yr = (const float*)(smem + SM_YS) + ((s) * TP + tid) * NFREQ; \
            __nv_bfloat16* yh = (__nv_bfloat16*)(smem + SM_YB + (buf) * YBSTRIDE) + tid * PY; \
            __nv_bfloat16* yl = (__nv_bfloat16*)(smem + SM_YB + (buf) * YBSTRIDE + HALFOFF) + tid * PY; \
            _Pragma("unroll")                                                    \
            for (int f = 0; f < NFREQ; ++f) {                                    \
                float v = yr[f];                                                 \
                __nv_bfloat16 h = __float2bfloat16(v);                           \
                yh[f] = h;                                                       \
                yl[f] = __float2bfloat16(v - __bfloat162float(h));               \
            }                                                                    \
        }

    // ---- init staging: biases, wout, zero Y pads, Y0/Y1 splits ----
    if (tid < TP) {
        ((float*)(smem + SM_FBB))[tid] = bftr[tid];
        ((float*)(smem + SM_FBB))[TP + tid] = bftr[HID + tid];
        ((float*)(smem + SM_CBB))[tid] = g_code[0][b][tid] + bfwd[tid];
        ((float*)(smem + SM_WOUT))[tid] = Wout[tid];
        #pragma unroll
        for (int bu = 0; bu < 2; ++bu) {
            __nv_bfloat16* yh = (__nv_bfloat16*)(smem + SM_YB + bu * YBSTRIDE) + tid * PY;
            __nv_bfloat16* yl = (__nv_bfloat16*)(smem + SM_YB + bu * YBSTRIDE + HALFOFF) + tid * PY;
            #pragma unroll
            for (int f = NFREQ; f < 16; ++f) { yh[f] = __float2bfloat16(0.f); yl[f] = __float2bfloat16(0.f); }
        }
        SPLIT_Y(0, 0);
        SPLIT_Y(1, 1);
    }
    CP_WAIT(0);      // F0, W0, F1 all landed
    __syncthreads();

    // lane address components
    const uint32_t aRow = (uint32_t)(lane & 15);
    const uint32_t aK8  = (uint32_t)((lane >> 4) * 8);
    const uint32_t bRow = (uint32_t)((lane & 7) + ((lane >> 4) & 1) * 8);
    const uint32_t bK8  = (uint32_t)(((lane >> 3) & 1) * 8);
    const uint32_t fRow = (uint32_t)(lane & 7);
    const uint32_t fK8  = (uint32_t)(((lane >> 3) & 1) * 8);

    const float* wos = (const float*)(smem + SM_WOUT);
    const int eRow = lane >> 2;
    const int eCol = (lane & 3) * 2;

    float fa[2][4][4];     // feature MMA results for the *current* layer's epilogue
    float os[4] = {0.f, 0.f, 0.f, 0.f};

    // ---- init: z0 = Y0*F0^T + fb0 -> Z;  then fa for layer 0 (shift 1) ----
    {
        const float* fb = (const float*)(smem + SM_FBB);   // buf0
        uint32_t Yh[2][4], Yl[2][4];
        #pragma unroll
        for (int mt = 0; mt < 2; ++mt) {
            uint32_t ro = (uint32_t)(m0w + mt * 16 + (int)aRow) * 48 + aK8 * 2;
            ldsm4(Yh[mt], sb + SM_YB + ro);
            ldsm4(Yl[mt], sb + SM_YB + HALFOFF + ro);
        }
        #pragma unroll
        for (int nt = 0; nt < 4; ++nt) {
            uint32_t fo = (uint32_t)(n0w + nt * 8 + (int)fRow) * 48 + fK8 * 2;
            uint32_t Fh[2], Fl[2];
            ldsm2(Fh, sb + SM_FT + fo);
            ldsm2(Fl, sb + SM_FT + HALFOFF + fo);
            #pragma unroll
            for (int mt = 0; mt < 2; ++mt) {
                float t4[4] = {0.f, 0.f, 0.f, 0.f};
                mma16816(t4, Yh[mt], Fh);
                mma16816(t4, Yh[mt], Fl);
                mma16816(t4, Yl[mt], Fh);
                int c0 = n0w + nt * 8 + eCol;
                int r0 = m0w + mt * 16 + eRow;
                float2 fbv = *(const float2*)&fb[c0];
                uint32_t hi, lo;
                uint32_t o0 = (uint32_t)(r0 * 272 + c0 * 2);
                uint32_t o1 = o0 + 8 * 272;
                split2(t4[0] + fbv.x, t4[1] + fbv.y, hi, lo);
                *(uint32_t*)(smem + SM_ZH + o0) = hi;
                *(uint32_t*)(smem + SM_ZL + o0) = lo;
                split2(t4[2] + fbv.x, t4[3] + fbv.y, hi, lo);
                *(uint32_t*)(smem + SM_ZH + o1) = hi;
                *(uint32_t*)(smem + SM_ZL + o1) = lo;
            }
        }
        // fa for layer 0 = shift 1 tiles (buf 1)
        #pragma unroll
        for (int mt = 0; mt < 2; ++mt) {
            uint32_t ro = (uint32_t)(m0w + mt * 16 + (int)aRow) * 48 + aK8 * 2;
            ldsm4(Yh[mt], sb + SM_YB + YBSTRIDE + ro);
            ldsm4(Yl[mt], sb + SM_YB + YBSTRIDE + HALFOFF + ro);
        }
        #pragma unroll
        for (int nt = 0; nt < 4; ++nt) {
            uint32_t fo = (uint32_t)(n0w + nt * 8 + (int)fRow) * 48 + fK8 * 2;
            uint32_t Fh[2], Fl[2];
            ldsm2(Fh, sb + SM_FT + YBSTRIDE + fo);
            ldsm2(Fl, sb + SM_FT + YBSTRIDE + HALFOFF + fo);
            #pragma unroll
            for (int mt = 0; mt < 2; ++mt) {
                fa[mt][nt][0] = fa[mt][nt][1] = fa[mt][nt][2] = fa[mt][nt][3] = 0.f;
                mma16816(fa[mt][nt], Yh[mt], Fh);
                mma16816(fa[mt][nt], Yh[mt], Fl);
                mma16816(fa[mt][nt], Yl[mt], Fh);
            }
        }
    }
    __syncthreads();

    // =========================== 5 fused layers =============================
    #pragma unroll 1
    for (int l = 0; l < DEPTH; ++l) {
        const int sbuf = l & 1;   // buffer for shift l+2 (staged now, fa'd at E2)

        // ---- A: stage shift l+2 F tiles + biases + Y split (no barrier) ----
        if (l <= 3) {
            const char* fs = (const char*)g_ft[l + 2];
            for (int i = tid; i < 768; i += NTHR)
                cpa16(sb + SM_FT + sbuf * YBSTRIDE + i * 16, fs + i * 16);
        }
        CP_COMMIT();
        if (tid < TP && l <= 3) {
            ((float*)(smem + SM_FBB))[sbuf * TP + tid] = bftr[(l + 2) * HID + tid];
            ((float*)(smem + SM_CBB))[((l + 1) & 1) * TP + tid] =
                g_code[l + 1][b][tid] + bfwd[(l + 1) * HID + tid];
            SPLIT_Y(l + 2, sbuf);
        }

        // ---- B: main GEMM (3-term split), warp tile 32x32 ----
        float acc[2][4][4];
        #pragma unroll
        for (int mt = 0; mt < 2; ++mt)
            #pragma unroll
            for (int nt = 0; nt < 4; ++nt)
                #pragma unroll
                for (int r = 0; r < 4; ++r) acc[mt][nt][r] = 0.f;

        #pragma unroll
        for (int ks = 0; ks < 8; ++ks) {
            const uint32_t k0 = ks * 16;
            uint32_t Ah[2][4], Al[2][4];
            #pragma unroll
            for (int mt = 0; mt < 2; ++mt) {
                uint32_t ro = (uint32_t)(m0w + mt * 16 + (int)aRow) * 272 + (k0 + aK8) * 2;
                ldsm4(Ah[mt], sb + SM_ZH + ro);
                ldsm4(Al[mt], sb + SM_ZL + ro);
            }
            #pragma unroll
            for (int np = 0; np < 2; ++np) {
                uint32_t ro = (uint32_t)(n0w + np * 16 + (int)bRow) * 272 + (k0 + bK8) * 2;
                uint32_t t[4];
                ldsm4(t, sb + SM_WH + ro);
                #pragma unroll
                for (int mt = 0; mt < 2; ++mt) {
                    mma16816(acc[mt][np * 2],     Ah[mt], t);
                    mma16816(acc[mt][np * 2 + 1], Ah[mt], t + 2);
                    mma16816(acc[mt][np * 2],     Al[mt], t);
                    mma16816(acc[mt][np * 2 + 1], Al[mt], t + 2);
                }
                ldsm4(t, sb + SM_WL + ro);
                #pragma unroll
                for (int mt = 0; mt < 2; ++mt) {
                    mma16816(acc[mt][np * 2],     Ah[mt], t);
                    mma16816(acc[mt][np * 2 + 1], Ah[mt], t + 2);
                }
            }
        }

        // ---- C: F[l+2] landed + all Z/W reads done ----
        CP_WAIT(0);
        __syncthreads();

        // ---- D: prefetch W[l+1] ----
        if (l + 1 < DEPTH) {
            const char* ws = (const char*)g_wt[l + 1];
            for (int i = tid; i < 4352; i += NTHR)
                cpa16(sb + SM_WH + i * 16, ws + i * 16);
        }
        CP_COMMIT();

        // ---- E: epilogue combine using fa (computed last iter) ----
        {
            const float* cbp = (const float*)(smem + SM_CBB) + (l & 1) * TP;
            const float* fbp = (const float*)(smem + SM_FBB) + ((l + 1) & 1) * TP;
            #pragma unroll
            for (int mt = 0; mt < 2; ++mt)
                #pragma unroll
                for (int nt = 0; nt < 4; ++nt) {
                    int c0 = n0w + nt * 8 + eCol;
                    int r0 = m0w + mt * 16 + eRow;
                    float2 fbv = *(const float2*)&fbp[c0];
                    float2 cbv = *(const float2*)&cbp[c0];
                    float z0 = (acc[mt][nt][0] + cbv.x) * (fa[mt][nt][0] + fbv.x);
                    float z1 = (acc[mt][nt][1] + cbv.y) * (fa[mt][nt][1] + fbv.y);
                    float z2 = (acc[mt][nt][2] + cbv.x) * (fa[mt][nt][2] + fbv.x);
                    float z3 = (acc[mt][nt][3] + cbv.y) * (fa[mt][nt][3] + fbv.y);
                    if (l < DEPTH - 1) {
                        uint32_t hi, lo;
                        uint32_t o0 = (uint32_t)(r0 * 272 + c0 * 2);
                        uint32_t o1 = o0 + 8 * 272;
                        split2(z0, z1, hi, lo);
                        *(uint32_t*)(smem + SM_ZH + o0) = hi;
                        *(uint32_t*)(smem + SM_ZL + o0) = lo;
                        split2(z2, z3, hi, lo);
                        *(uint32_t*)(smem + SM_ZH + o1) = hi;
                        *(uint32_t*)(smem + SM_ZL + o1) = lo;
                    } else {
                        float2 wv = *(const float2*)&wos[c0];
                        os[mt * 2 + 0] = fmaf(z0, wv.x, fmaf(z1, wv.y, os[mt * 2 + 0]));
                        os[mt * 2 + 1] = fmaf(z2, wv.x, fmaf(z3, wv.y, os[mt * 2 + 1]));
                    }
                }
        }

        // ---- E2: compute fa for next layer (shift l+2, buf sbuf) ----
        if (l < DEPTH - 1) {
            uint32_t Yh[2][4], Yl[2][4];
            uint32_t yb = sb + SM_YB + sbuf * YBSTRIDE;
            uint32_t ft = sb + SM_FT + sbuf * YBSTRIDE;
            #pragma unroll
            for (int mt = 0; mt < 2; ++mt) {
                uint32_t ro = (uint32_t)(m0w + mt * 16 + (int)aRow) * 48 + aK8 * 2;
                ldsm4(Yh[mt], yb + ro);
                ldsm4(Yl[mt], yb + HALFOFF + ro);
            }
            #pragma unroll
            for (int nt = 0; nt < 4; ++nt) {
                uint32_t fo = (uint32_t)(n0w + nt * 8 + (int)fRow) * 48 + fK8 * 2;
                uint32_t Fh[2], Fl[2];
                ldsm2(Fh, ft + fo);
                ldsm2(Fl, ft + HALFOFF + fo);
                #pragma unroll
                for (int mt = 0; mt < 2; ++mt) {
                    fa[mt][nt][0] = fa[mt][nt][1] = fa[mt][nt][2] = fa[mt][nt][3] = 0.f;
                    mma16816(fa[mt][nt], Yh[mt], Fh);
                    mma16816(fa[mt][nt], Yh[mt], Fl);
                    mma16816(fa[mt][nt], Yl[mt], Fh);
                }
            }
        }

        // ---- G: W[l+1] landed; publish Z/fa buffers ----
        CP_WAIT(0);
        __syncthreads();
    }

    // ---- output reduce: 4 warpG partials ----
    {
        #pragma unroll
        for (int i = 0; i < 4; ++i) {
            os[i] += __shfl_xor_sync(0xffffffffu, os[i], 1);
            os[i] += __shfl_xor_sync(0xffffffffu, os[i], 2);
        }
        float* outp = (float*)(smem + SM_OUTP);
        if ((lane & 3) == 0) {
            #pragma unroll
            for (int mt = 0; mt < 2; ++mt) {
                outp[warpG * TP + m0w + mt * 16 + eRow]     = os[mt * 2 + 0];
                outp[warpG * TP + m0w + mt * 16 + 8 + eRow] = os[mt * 2 + 1];
            }
        }
        __syncthreads();
        if (tid < TP)
            out[pt0 + tid] = outp[tid] + outp[TP + tid] + outp[2 * TP + tid] +
                             outp[3 * TP + tid] + *bout;
    }
}

// ---------------------------------------------------------------------------
extern "C" void kernel_launch(void* const* d_in, const int* in_sizes, int n_in,
                              void* d_out, int out_size) {
    const float* x     = (const float*)d_in[0];
    const float* a     = (const float*)d_in[1];
    const float* Wftr  = (const float*)d_in[2];
    const float* bftr  = (const float*)d_in[3];
    const float* Wfwd  = (const float*)d_in[4];
    const float* bfwd  = (const float*)d_in[5];
    const float* Wcode = (const float*)d_in[6];
    const float* bcode = (const float*)d_in[7];
    const float* Wout  = (const float*)d_in[8];
    const float* bout  = (const float*)d_in[9];
    float* out = (float*)d_out;

    prep_all<<<NCODE_BLK + NW_BLK, 256>>>(a, Wcode, bcode, Wfwd, Wftr);

    cudaFuncSetAttribute(sinr_mma, cudaFuncAttributeMaxDynamicSharedMemorySize,
                         SM_TOTAL);
    sinr_mma<<<TOTAL_PTS / TP, NTHR, SM_TOTAL>>>(x, bftr, bfwd, Wout, bout, out);

    if (out_size >= TOTAL_PTS + in_sizes[0]) {
        cudaMemcpyAsync(out + TOTAL_PTS, x, (size_t)in_sizes[0] * sizeof(float),
                        cudaMemcpyDeviceToDevice);
    }
}